// round 2
// baseline (speedup 1.0000x reference)
#include <cuda_runtime.h>

#define NB 4
#define BATCH 1024
#define EPS 1e-5f

// Scratch (no allocations allowed). 16B-aligned for vectorized access.
__device__ __align__(16) float g_psi[BATCH * 16];
__device__ __align__(16) float g_psip[BATCH * 16];
__device__ __align__(16) float g_H8[BATCH * 8 * 8];      // [j][m][k] evolving h for columns m<8
__device__ __align__(16) float g_attn[NB * BATCH * 8];   // [t][j][k]
__device__ __align__(16) float g_ffn[NB * BATCH * 8];    // [t][j][k]
__device__ __align__(16) float g_part[16 * BATCH * 8];   // [jblock][i][k] partial pooled sums

// Forward CNOT-ladder permutation for n=4: (0,1),(1,2),(2,3),(3,0)
__device__ __forceinline__ int fwd4(int m) {
    int idx = m;
    idx ^= ((idx >> 3) & 1) << 2;
    idx ^= ((idx >> 2) & 1) << 1;
    idx ^= ((idx >> 1) & 1) << 0;
    idx ^= ((idx >> 0) & 1) << 3;
    return idx;
}

__device__ __forceinline__ void ln8(float h[8], const float* g, const float* b) {
    float m = 0.f;
#pragma unroll
    for (int k = 0; k < 8; k++) m += h[k];
    m *= 0.125f;
    float v = 0.f;
#pragma unroll
    for (int k = 0; k < 8; k++) { float d = h[k] - m; v += d * d; }
    float rs = rsqrtf(v * 0.125f + EPS);
#pragma unroll
    for (int k = 0; k < 8; k++) h[k] = (h[k] - m) * rs * g[k] + b[k];
}

// attn[w>=1] = z0*...*zw ; attn[0] = z1*...*z7   (GF(2)-linear ladder + product state)
__device__ __forceinline__ void attn8(const float z[8], float a[8]) {
    float p = z[0];
#pragma unroll
    for (int w = 1; w < 8; w++) { p *= z[w]; a[w] = p; }
    float q = z[1];
#pragma unroll
    for (int w = 2; w < 8; w++) q *= z[w];
    a[0] = q;
}

// ---------------- Phase A: product states ----------------
__global__ void k_psi(const float* __restrict__ x) {
    int i = blockIdx.x * blockDim.x + threadIdx.x;
    if (i >= BATCH) return;
    float c[4], s[4];
#pragma unroll
    for (int w = 0; w < 4; w++) { float h = 0.5f * x[i * 4 + w]; c[w] = cosf(h); s[w] = sinf(h); }
    float p[16];
#pragma unroll
    for (int m = 0; m < 16; m++) {
        float v = (((m >> 3) & 1) ? s[0] : c[0]) * (((m >> 2) & 1) ? s[1] : c[1]) *
                  (((m >> 1) & 1) ? s[2] : c[2]) * (((m >> 0) & 1) ? s[3] : c[3]);
        p[m] = v;
        g_psi[i * 16 + m] = v;
    }
#pragma unroll
    for (int m = 0; m < 16; m++) g_psip[i * 16 + m] = p[fwd4(m)];
}

// ---------------- Phase B: per-column recurrences (columns 0..7 tracked in H8) ----------------
__global__ void k_init_attn(const float* __restrict__ proj_w, const float* __restrict__ proj_b,
                            const float* __restrict__ rx) {
    int j = blockIdx.x * blockDim.x + threadIdx.x;
    if (j >= BATCH) return;
    float psi[16];
#pragma unroll
    for (int u = 0; u < 16; u++) psi[u] = g_psi[j * 16 + u];
    float pw[8], pb[8];
#pragma unroll
    for (int k = 0; k < 8; k++) { pw[k] = proj_w[k]; pb[k] = proj_b[k]; }
    float z[8];
#pragma unroll
    for (int m = 0; m < 8; m++) {
        float d = 0.f;
#pragma unroll
        for (int u = 0; u < 16; u++) d += psi[u] * g_psip[m * 16 + u];
        float gr = fabsf(d);
#pragma unroll
        for (int k = 0; k < 8; k++) g_H8[(j * 8 + m) * 8 + k] = gr * pw[k] + pb[k];
        z[m] = cosf(rx[m]) * cosf(gr * pw[0] + pb[0]);
    }
    float a[8];
    attn8(z, a);
#pragma unroll
    for (int w = 0; w < 8; w++) g_attn[j * 8 + w] = a[w];
}

__global__ void k_ln1_ffn(int t, const float* __restrict__ ry, const float* __restrict__ ffn_w,
                          const float* __restrict__ ffn_b, const float* __restrict__ ln1_g,
                          const float* __restrict__ ln1_b) {
    int j = blockIdx.x * blockDim.x + threadIdx.x;
    if (j >= BATCH) return;
    const float* at = g_attn + (size_t)t * BATCH * 8;
    float g1[8], b1[8];
#pragma unroll
    for (int k = 0; k < 8; k++) { g1[k] = ln1_g[t * 8 + k]; b1[k] = ln1_b[t * 8 + k]; }
    float meas[8];
#pragma unroll
    for (int m = 0; m < 8; m++) {
        float h[8];
#pragma unroll
        for (int k = 0; k < 8; k++) h[k] = g_H8[(j * 8 + m) * 8 + k] + at[m * 8 + k];
        ln8(h, g1, b1);
#pragma unroll
        for (int k = 0; k < 8; k++) g_H8[(j * 8 + m) * 8 + k] = h[k];
        float mm = cosf(h[0] + ry[t * 8 + m]);
        meas[m] = mm > 0.f ? mm : 0.f;   // relu(cos(...))
    }
#pragma unroll
    for (int m = 0; m < 8; m++) {
        float s = ffn_b[t * 8 + m];
#pragma unroll
        for (int f = 0; f < 8; f++) s += meas[f] * ffn_w[t * 64 + m * 8 + f];
        g_ffn[(size_t)t * BATCH * 8 + j * 8 + m] = s;
    }
}

__global__ void k_ln2_attn(int t, const float* __restrict__ rx, const float* __restrict__ ln2_g,
                           const float* __restrict__ ln2_b) {
    int j = blockIdx.x * blockDim.x + threadIdx.x;
    if (j >= BATCH) return;
    const float* ft = g_ffn + (size_t)t * BATCH * 8;
    float g2[8], b2[8];
#pragma unroll
    for (int k = 0; k < 8; k++) { g2[k] = ln2_g[t * 8 + k]; b2[k] = ln2_b[t * 8 + k]; }
    float z[8];
#pragma unroll
    for (int m = 0; m < 8; m++) {
        float h[8];
#pragma unroll
        for (int k = 0; k < 8; k++) h[k] = g_H8[(j * 8 + m) * 8 + k] + ft[m * 8 + k];
        ln8(h, g2, b2);
#pragma unroll
        for (int k = 0; k < 8; k++) g_H8[(j * 8 + m) * 8 + k] = h[k];
        z[m] = cosf(rx[(t + 1) * 8 + m]) * cosf(h[0]);
    }
    float a[8];
    attn8(z, a);
#pragma unroll
    for (int w = 0; w < 8; w++) g_attn[(size_t)(t + 1) * BATCH * 8 + j * 8 + w] = a[w];
}

// ---------------- Final sweep: 1024x1024 elements, h never materialized ----------------
__global__ void k_final(const float* __restrict__ proj_w, const float* __restrict__ proj_b,
                        const float* __restrict__ ln1_g, const float* __restrict__ ln1_b,
                        const float* __restrict__ ln2_g, const float* __restrict__ ln2_b) {
    __shared__ float sPsiP[64][16];
    __shared__ float sAttn[NB][64][8];
    __shared__ float sFfn[NB][64][8];
    __shared__ float sPW[8], sPB[8];
    __shared__ float sL1G[NB][8], sL1B[NB][8], sL2G[NB][8], sL2B[NB][8];
    __shared__ float sRed[8][32][8];

    int jb = blockIdx.x;            // 16 j-blocks of 64 columns
    int ib = blockIdx.y;            // 32 i-blocks of 32 rows
    int tid = threadIdx.x;          // 256 threads = 8 warps
    int lane = tid & 31, w = tid >> 5;
    int j0 = jb * 64;
    int i = ib * 32 + lane;

    for (int u = tid; u < 64 * 16; u += 256) sPsiP[u >> 4][u & 15] = g_psip[j0 * 16 + u];
    for (int u = tid; u < NB * 64 * 8; u += 256) {
        int t = u >> 9; int r = u & 511;
        sAttn[t][r >> 3][r & 7] = g_attn[(size_t)t * BATCH * 8 + j0 * 8 + r];
        sFfn[t][r >> 3][r & 7] = g_ffn[(size_t)t * BATCH * 8 + j0 * 8 + r];
    }
    if (tid < 8) { sPW[tid] = proj_w[tid]; sPB[tid] = proj_b[tid]; }
    if (tid < NB * 8) {
        sL1G[tid >> 3][tid & 7] = ln1_g[tid];
        sL1B[tid >> 3][tid & 7] = ln1_b[tid];
        sL2G[tid >> 3][tid & 7] = ln2_g[tid];
        sL2B[tid >> 3][tid & 7] = ln2_b[tid];
    }
    __syncthreads();

    float psi[16];
    const float4* pp = (const float4*)(g_psi + (size_t)i * 16);
#pragma unroll
    for (int q = 0; q < 4; q++) {
        float4 v = pp[q];
        psi[4 * q] = v.x; psi[4 * q + 1] = v.y; psi[4 * q + 2] = v.z; psi[4 * q + 3] = v.w;
    }

    float acc[8];
#pragma unroll
    for (int k = 0; k < 8; k++) acc[k] = 0.f;

    for (int jj = 0; jj < 8; jj++) {
        int jc = w * 8 + jj;        // warp-uniform -> LDS broadcasts
        float d = 0.f;
#pragma unroll
        for (int u = 0; u < 16; u++) d += psi[u] * sPsiP[jc][u];
        float g = fabsf(d);
        float h[8];
#pragma unroll
        for (int k = 0; k < 8; k++) h[k] = g * sPW[k] + sPB[k];
#pragma unroll
        for (int t = 0; t < NB; t++) {
#pragma unroll
            for (int k = 0; k < 8; k++) h[k] += sAttn[t][jc][k];
            ln8(h, sL1G[t], sL1B[t]);
#pragma unroll
            for (int k = 0; k < 8; k++) h[k] += sFfn[t][jc][k];
            ln8(h, sL2G[t], sL2B[t]);
        }
#pragma unroll
        for (int k = 0; k < 8; k++) acc[k] += h[k];
    }

#pragma unroll
    for (int k = 0; k < 8; k++) sRed[w][lane][k] = acc[k];
    __syncthreads();
    {
        int il = tid >> 3, k = tid & 7;     // 256 threads = 32 rows x 8 channels
        float s = 0.f;
#pragma unroll
        for (int ww = 0; ww < 8; ww++) s += sRed[ww][il][k];
        g_part[(size_t)jb * BATCH * 8 + (size_t)(ib * 32 + il) * 8 + k] = s;
    }
}

__global__ void k_reduce(const float* __restrict__ cls_w, const float* __restrict__ cls_b,
                         float* __restrict__ out) {
    int i = blockIdx.x * blockDim.x + threadIdx.x;
    if (i >= BATCH) return;
    float p[8];
#pragma unroll
    for (int k = 0; k < 8; k++) p[k] = 0.f;
    for (int jb = 0; jb < 16; jb++)
#pragma unroll
        for (int k = 0; k < 8; k++) p[k] += g_part[(size_t)jb * BATCH * 8 + (size_t)i * 8 + k];
#pragma unroll
    for (int k = 0; k < 8; k++) p[k] *= (1.0f / BATCH);
#pragma unroll
    for (int c = 0; c < 10; c++) {
        float s = cls_b[c];
#pragma unroll
        for (int k = 0; k < 8; k++) s += p[k] * cls_w[c * 8 + k];
        out[i * 10 + c] = s;
    }
}

extern "C" void kernel_launch(void* const* d_in, const int* in_sizes, int n_in,
                              void* d_out, int out_size) {
    const float* x      = (const float*)d_in[0];
    const float* proj_w = (const float*)d_in[1];
    const float* proj_b = (const float*)d_in[2];
    const float* rx     = (const float*)d_in[3];
    const float* ry     = (const float*)d_in[4];
    const float* ffn_w  = (const float*)d_in[5];
    const float* ffn_b  = (const float*)d_in[6];
    const float* ln1_g  = (const float*)d_in[7];
    const float* ln1_b  = (const float*)d_in[8];
    const float* ln2_g  = (const float*)d_in[9];
    const float* ln2_b  = (const float*)d_in[10];
    const float* cls_w  = (const float*)d_in[11];
    const float* cls_b  = (const float*)d_in[12];
    float* out = (float*)d_out;

    k_psi<<<4, 256>>>(x);
    k_init_attn<<<4, 256>>>(proj_w, proj_b, rx);
    for (int t = 0; t < NB; t++) {
        k_ln1_ffn<<<4, 256>>>(t, ry, ffn_w, ffn_b, ln1_g, ln1_b);
        if (t < NB - 1) k_ln2_attn<<<4, 256>>>(t, rx, ln2_g, ln2_b);
    }
    k_final<<<dim3(16, 32), 256>>>(proj_w, proj_b, ln1_g, ln1_b, ln2_g, ln2_b);
    k_reduce<<<4, 256>>>(cls_w, cls_b, out);
}

// round 4
// speedup vs baseline: 1.9258x; 1.9258x over previous
#include <cuda_runtime.h>

#define NB 4
#define BATCH 1024
#define EPS 1e-5f

// Scratch (no allocations allowed). 16B-aligned for vectorized access.
__device__ __align__(16) float g_psi[BATCH * 16];
__device__ __align__(16) float g_psip[BATCH * 16];
__device__ __align__(16) float g_attn[NB * BATCH * 8];   // [t][j][k]
__device__ __align__(16) float g_ffn[NB * BATCH * 8];    // [t][j][k]
__device__ __align__(16) float g_part[16 * BATCH * 8];   // [jblock][i][k]

// Forward CNOT-ladder permutation for n=4: (0,1),(1,2),(2,3),(3,0)
__device__ __forceinline__ int fwd4(int m) {
    int idx = m;
    idx ^= ((idx >> 3) & 1) << 2;
    idx ^= ((idx >> 2) & 1) << 1;
    idx ^= ((idx >> 1) & 1) << 0;
    idx ^= ((idx >> 0) & 1) << 3;
    return idx;
}

__device__ __forceinline__ void ln8(float h[8], const float* g, const float* b) {
    float m = 0.f;
#pragma unroll
    for (int k = 0; k < 8; k++) m += h[k];
    m *= 0.125f;
    float v = 0.f;
#pragma unroll
    for (int k = 0; k < 8; k++) { float d = h[k] - m; v += d * d; }
    float rs = rsqrtf(v * 0.125f + EPS);
#pragma unroll
    for (int k = 0; k < 8; k++) h[k] = (h[k] - m) * rs * g[k] + b[k];
}

// attn[w>=1] = z0*...*zw ; attn[0] = z1*...*z7
__device__ __forceinline__ void attn8(const float z[8], float a[8]) {
    float p = z[0];
#pragma unroll
    for (int w = 1; w < 8; w++) { p *= z[w]; a[w] = p; }
    float q = z[1];
#pragma unroll
    for (int w = 2; w < 8; w++) q *= z[w];
    a[0] = q;
}

__device__ __forceinline__ void psi16(const float* __restrict__ x, int row, float p[16]) {
    float c[4], s[4];
#pragma unroll
    for (int w = 0; w < 4; w++) {
        float hh = 0.5f * x[row * 4 + w];
        c[w] = cosf(hh); s[w] = sinf(hh);
    }
#pragma unroll
    for (int m = 0; m < 16; m++) {
        p[m] = (((m >> 3) & 1) ? s[0] : c[0]) * (((m >> 2) & 1) ? s[1] : c[1]) *
               (((m >> 1) & 1) ? s[2] : c[2]) * (((m >> 0) & 1) ? s[3] : c[3]);
    }
}

// ---------------- Fused sequential phase ----------------
// Phase 0: threads 0..63 solve the closed 8x8 system (rows 0..7 x tracked cols 0..7),
//          persisting per-stage consts sA[t][m][k] (=attn[m][k]) and sF[t][m][k] (=ffn[m][k]).
// Phase 1: one thread per (row j, tracked col m): evolve h[j][m][:] with those consts,
//          store own attn[j][m], ffn[j][m] for k_final.
__global__ void k_phaseB(const float* __restrict__ x,
                         const float* __restrict__ proj_w, const float* __restrict__ proj_b,
                         const float* __restrict__ rx, const float* __restrict__ ry,
                         const float* __restrict__ ffn_w, const float* __restrict__ ffn_b,
                         const float* __restrict__ ln1_g, const float* __restrict__ ln1_b,
                         const float* __restrict__ ln2_g, const float* __restrict__ ln2_b) {
    __shared__ float sRx[NB * 8], sRy[NB * 8];
    __shared__ float sFw[NB * 64], sFb[NB * 8];
    __shared__ float sL1G[NB * 8], sL1B[NB * 8], sL2G[NB * 8], sL2B[NB * 8];
    __shared__ float sPW[8], sPB[8];
    __shared__ float sA[NB][8][9];   // attn of rows 0..7 per stage (padded: no bank conflict)
    __shared__ float sF[NB][8][9];   // ffn  of rows 0..7 per stage

    int tid = threadIdx.x;
    if (tid < NB * 8) {
        sRx[tid] = rx[tid]; sRy[tid] = ry[tid]; sFb[tid] = ffn_b[tid];
        sL1G[tid] = ln1_g[tid]; sL1B[tid] = ln1_b[tid];
        sL2G[tid] = ln2_g[tid]; sL2B[tid] = ln2_b[tid];
    }
    if (tid < 8) { sPW[tid] = proj_w[tid]; sPB[tid] = proj_b[tid]; }
    for (int u = tid; u < NB * 64; u += blockDim.x) sFw[u] = ffn_w[u];
    __syncthreads();

    int lane = tid & 31;
    int rowbase = lane & 24;
    const unsigned mask = 0xFFFFFFFFu;

    // ================= Phase 0 =================
    bool p0 = (tid < 64);
    int j0 = tid >> 3;   // row 0..7 (when p0)
    int m0 = tid & 7;    // col 0..7
    float h0[8];
    if (p0) {
        float pj[16], pr[16];
        psi16(x, j0, pj);
        psi16(x, m0, pr);
        float d = 0.f;
#pragma unroll
        for (int u = 0; u < 16; u++) d += pj[u] * pr[fwd4(u)];
        float gr = fabsf(d);
#pragma unroll
        for (int k = 0; k < 8; k++) h0[k] = gr * sPW[k] + sPB[k];
    }
#pragma unroll
    for (int t = 0; t < NB; t++) {
        if (p0) {
            float z = cosf(sRx[t * 8 + m0]) * cosf(h0[0]);
            float zz[8];
#pragma unroll
            for (int u = 0; u < 8; u++) zz[u] = __shfl_sync(mask, z, rowbase | u);
            float a[8];
            attn8(zz, a);
            sA[t][j0][m0] = a[m0];     // attn[row j0][component m0]
        }
        __syncthreads();
        if (p0) {
#pragma unroll
            for (int k = 0; k < 8; k++) h0[k] += sA[t][m0][k];   // += attn[col m0][k]
            ln8(h0, sL1G + t * 8, sL1B + t * 8);
            float mv = cosf(h0[0] + sRy[t * 8 + m0]);
            mv = mv > 0.f ? mv : 0.f;
            float mm[8];
#pragma unroll
            for (int u = 0; u < 8; u++) mm[u] = __shfl_sync(mask, mv, rowbase | u);
            float s = sFb[t * 8 + m0];
#pragma unroll
            for (int u = 0; u < 8; u++) s += mm[u] * sFw[t * 64 + m0 * 8 + u];
            sF[t][j0][m0] = s;         // ffn[row j0][component m0]
        }
        __syncthreads();
        if (p0) {
#pragma unroll
            for (int k = 0; k < 8; k++) h0[k] += sF[t][m0][k];   // += ffn[col m0][k]
            ln8(h0, sL2G + t * 8, sL2B + t * 8);
        }
    }
    // All sA/sF writes are covered by the last __syncthreads above.

    // ================= Phase 1 =================
    int gid = blockIdx.x * blockDim.x + tid;
    int j = gid >> 3;           // row 0..1023
    int m = gid & 7;            // tracked column 0..7

    float psi[16];
    psi16(x, j, psi);
    {
        float pr[16];
        psi16(x, m, pr);
        float d = 0.f;
#pragma unroll
        for (int u = 0; u < 16; u++) d += psi[u] * pr[fwd4(u)];
        float gr = fabsf(d);
        float h[8];
#pragma unroll
        for (int k = 0; k < 8; k++) h[k] = gr * sPW[k] + sPB[k];

        // thread m==0 publishes psi_j / permuted psi_j for k_final
        if (m == 0) {
            float pp[16];
#pragma unroll
            for (int u = 0; u < 16; u++) pp[u] = psi[fwd4(u)];
            float4* po = (float4*)(g_psi + (size_t)j * 16);
            float4* pq = (float4*)(g_psip + (size_t)j * 16);
#pragma unroll
            for (int q = 0; q < 4; q++) {
                po[q] = make_float4(psi[4 * q], psi[4 * q + 1], psi[4 * q + 2], psi[4 * q + 3]);
                pq[q] = make_float4(pp[4 * q], pp[4 * q + 1], pp[4 * q + 2], pp[4 * q + 3]);
            }
        }

#pragma unroll
        for (int t = 0; t < NB; t++) {
            // own attn[j][m], from this row's 8 z-values
            float z = cosf(sRx[t * 8 + m]) * cosf(h[0]);
            float zz[8];
#pragma unroll
            for (int u = 0; u < 8; u++) zz[u] = __shfl_sync(mask, z, rowbase | u);
            float a[8];
            attn8(zz, a);
            g_attn[(size_t)t * BATCH * 8 + (size_t)j * 8 + m] = a[m];

#pragma unroll
            for (int k = 0; k < 8; k++) h[k] += sA[t][m][k];
            ln8(h, sL1G + t * 8, sL1B + t * 8);

            // own ffn[j][m] component only (one row of the 8x8 matvec)
            float mv = cosf(h[0] + sRy[t * 8 + m]);
            mv = mv > 0.f ? mv : 0.f;
            float mm[8];
#pragma unroll
            for (int u = 0; u < 8; u++) mm[u] = __shfl_sync(mask, mv, rowbase | u);
            float s = sFb[t * 8 + m];
#pragma unroll
            for (int u = 0; u < 8; u++) s += mm[u] * sFw[t * 64 + m * 8 + u];
            g_ffn[(size_t)t * BATCH * 8 + (size_t)j * 8 + m] = s;

#pragma unroll
            for (int k = 0; k < 8; k++) h[k] += sF[t][m][k];
            ln8(h, sL2G + t * 8, sL2B + t * 8);
        }
    }
}

// ---------------- Final sweep: 1024x1024 elements, h never materialized ----------------
__global__ void k_final(const float* __restrict__ proj_w, const float* __restrict__ proj_b,
                        const float* __restrict__ ln1_g, const float* __restrict__ ln1_b,
                        const float* __restrict__ ln2_g, const float* __restrict__ ln2_b) {
    __shared__ float sPsiP[64][16];
    __shared__ float sAttn[NB][64][8];
    __shared__ float sFfn[NB][64][8];
    __shared__ float sPW[8], sPB[8];
    __shared__ float sL1G[NB][8], sL1B[NB][8], sL2G[NB][8], sL2B[NB][8];
    __shared__ float sRed[8][32][8];

    int jb = blockIdx.x;            // 16 j-blocks of 64 columns
    int ib = blockIdx.y;            // 32 i-blocks of 32 rows
    int tid = threadIdx.x;          // 256 threads = 8 warps
    int lane = tid & 31, w = tid >> 5;
    int j0 = jb * 64;
    int i = ib * 32 + lane;

    for (int u = tid; u < 64 * 16; u += 256) sPsiP[u >> 4][u & 15] = g_psip[j0 * 16 + u];
    for (int u = tid; u < NB * 64 * 8; u += 256) {
        int t = u >> 9; int r = u & 511;
        sAttn[t][r >> 3][r & 7] = g_attn[(size_t)t * BATCH * 8 + j0 * 8 + r];
        sFfn[t][r >> 3][r & 7] = g_ffn[(size_t)t * BATCH * 8 + j0 * 8 + r];
    }
    if (tid < 8) { sPW[tid] = proj_w[tid]; sPB[tid] = proj_b[tid]; }
    if (tid < NB * 8) {
        sL1G[tid >> 3][tid & 7] = ln1_g[tid];
        sL1B[tid >> 3][tid & 7] = ln1_b[tid];
        sL2G[tid >> 3][tid & 7] = ln2_g[tid];
        sL2B[tid >> 3][tid & 7] = ln2_b[tid];
    }
    __syncthreads();

    float psi[16];
    const float4* pp = (const float4*)(g_psi + (size_t)i * 16);
#pragma unroll
    for (int q = 0; q < 4; q++) {
        float4 v = pp[q];
        psi[4 * q] = v.x; psi[4 * q + 1] = v.y; psi[4 * q + 2] = v.z; psi[4 * q + 3] = v.w;
    }

    float acc[8];
#pragma unroll
    for (int k = 0; k < 8; k++) acc[k] = 0.f;

#pragma unroll 2
    for (int jj = 0; jj < 8; jj++) {
        int jc = w * 8 + jj;        // warp-uniform -> LDS broadcasts
        float d = 0.f;
#pragma unroll
        for (int u = 0; u < 16; u++) d += psi[u] * sPsiP[jc][u];
        float g = fabsf(d);
        float h[8];
#pragma unroll
        for (int k = 0; k < 8; k++) h[k] = g * sPW[k] + sPB[k];
#pragma unroll
        for (int t = 0; t < NB; t++) {
#pragma unroll
            for (int k = 0; k < 8; k++) h[k] += sAttn[t][jc][k];
            ln8(h, sL1G[t], sL1B[t]);
#pragma unroll
            for (int k = 0; k < 8; k++) h[k] += sFfn[t][jc][k];
            ln8(h, sL2G[t], sL2B[t]);
        }
#pragma unroll
        for (int k = 0; k < 8; k++) acc[k] += h[k];
    }

#pragma unroll
    for (int k = 0; k < 8; k++) sRed[w][lane][k] = acc[k];
    __syncthreads();
    {
        int il = tid >> 3, k = tid & 7;     // 256 threads = 32 rows x 8 channels
        float s = 0.f;
#pragma unroll
        for (int ww = 0; ww < 8; ww++) s += sRed[ww][il][k];
        g_part[(size_t)jb * BATCH * 8 + (size_t)(ib * 32 + il) * 8 + k] = s;
    }
}

__global__ void k_reduce(const float* __restrict__ cls_w, const float* __restrict__ cls_b,
                         float* __restrict__ out) {
    int i = blockIdx.x * blockDim.x + threadIdx.x;
    if (i >= BATCH) return;
    float p[8];
#pragma unroll
    for (int k = 0; k < 8; k++) p[k] = 0.f;
    for (int jb = 0; jb < 16; jb++) {
        const float4* q = (const float4*)(g_part + (size_t)jb * BATCH * 8 + (size_t)i * 8);
        float4 v0 = q[0], v1 = q[1];
        p[0] += v0.x; p[1] += v0.y; p[2] += v0.z; p[3] += v0.w;
        p[4] += v1.x; p[5] += v1.y; p[6] += v1.z; p[7] += v1.w;
    }
#pragma unroll
    for (int k = 0; k < 8; k++) p[k] *= (1.0f / BATCH);
#pragma unroll
    for (int c = 0; c < 10; c++) {
        float s = cls_b[c];
#pragma unroll
        for (int k = 0; k < 8; k++) s += p[k] * cls_w[c * 8 + k];
        out[i * 10 + c] = s;
    }
}

extern "C" void kernel_launch(void* const* d_in, const int* in_sizes, int n_in,
                              void* d_out, int out_size) {
    const float* x      = (const float*)d_in[0];
    const float* proj_w = (const float*)d_in[1];
    const float* proj_b = (const float*)d_in[2];
    const float* rx     = (const float*)d_in[3];
    const float* ry     = (const float*)d_in[4];
    const float* ffn_w  = (const float*)d_in[5];
    const float* ffn_b  = (const float*)d_in[6];
    const float* ln1_g  = (const float*)d_in[7];
    const float* ln1_b  = (const float*)d_in[8];
    const float* ln2_g  = (const float*)d_in[9];
    const float* ln2_b  = (const float*)d_in[10];
    const float* cls_w  = (const float*)d_in[11];
    const float* cls_b  = (const float*)d_in[12];
    float* out = (float*)d_out;

    k_phaseB<<<32, 256>>>(x, proj_w, proj_b, rx, ry, ffn_w, ffn_b,
                          ln1_g, ln1_b, ln2_g, ln2_b);
    k_final<<<dim3(16, 32), 256>>>(proj_w, proj_b, ln1_g, ln1_b, ln2_g, ln2_b);
    k_reduce<<<16, 64>>>(cls_w, cls_b, out);
}

// round 5
// speedup vs baseline: 2.4233x; 1.2583x over previous
#include <cuda_runtime.h>

#define NB 4
#define BATCH 1024
#define EPS 1e-5f

// Scratch (no allocations allowed). 16B-aligned for vectorized access.
__device__ __align__(16) float g_psi[BATCH * 16];
__device__ __align__(16) float g_psip[BATCH * 16];
__device__ __align__(16) float g_attn[NB * BATCH * 8];   // [t][j][k]
__device__ __align__(16) float g_ffn[NB * BATCH * 8];    // [t][j][k]
__device__ __align__(16) float g_part[16 * BATCH * 8];   // [jblock][i][k]

// Forward CNOT-ladder permutation for n=4: (0,1),(1,2),(2,3),(3,0)
__device__ __forceinline__ int fwd4(int m) {
    int idx = m;
    idx ^= ((idx >> 3) & 1) << 2;
    idx ^= ((idx >> 2) & 1) << 1;
    idx ^= ((idx >> 1) & 1) << 0;
    idx ^= ((idx >> 0) & 1) << 3;
    return idx;
}

// LayerNorm over 8 channels, tree-structured reductions (log-depth latency)
__device__ __forceinline__ void ln8(float h[8], const float* g, const float* b) {
    float m = ((h[0] + h[1]) + (h[2] + h[3])) + ((h[4] + h[5]) + (h[6] + h[7]));
    m *= 0.125f;
    float d0 = h[0] - m, d1 = h[1] - m, d2 = h[2] - m, d3 = h[3] - m;
    float d4 = h[4] - m, d5 = h[5] - m, d6 = h[6] - m, d7 = h[7] - m;
    float v = ((d0 * d0 + d1 * d1) + (d2 * d2 + d3 * d3)) +
              ((d4 * d4 + d5 * d5) + (d6 * d6 + d7 * d7));
    float rs = rsqrtf(v * 0.125f + EPS);
    h[0] = d0 * rs * g[0] + b[0]; h[1] = d1 * rs * g[1] + b[1];
    h[2] = d2 * rs * g[2] + b[2]; h[3] = d3 * rs * g[3] + b[3];
    h[4] = d4 * rs * g[4] + b[4]; h[5] = d5 * rs * g[5] + b[5];
    h[6] = d6 * rs * g[6] + b[6]; h[7] = d7 * rs * g[7] + b[7];
}

// attn[w>=1] = z0*...*zw ; attn[0] = z1*...*z7
__device__ __forceinline__ void attn8(const float z[8], float a[8]) {
    float p = z[0];
#pragma unroll
    for (int w = 1; w < 8; w++) { p *= z[w]; a[w] = p; }
    float q = z[1];
#pragma unroll
    for (int w = 2; w < 8; w++) q *= z[w];
    a[0] = q;
}

__device__ __forceinline__ void psi16(const float* __restrict__ x, int row, float p[16]) {
    float c[4], s[4];
#pragma unroll
    for (int w = 0; w < 4; w++) {
        float hh = 0.5f * x[row * 4 + w];
        c[w] = __cosf(hh); s[w] = __sinf(hh);
    }
#pragma unroll
    for (int m = 0; m < 16; m++) {
        p[m] = (((m >> 3) & 1) ? s[0] : c[0]) * (((m >> 2) & 1) ? s[1] : c[1]) *
               (((m >> 1) & 1) ? s[2] : c[2]) * (((m >> 0) & 1) ? s[3] : c[3]);
    }
}

// ---------------- Fused sequential phase, interleaved ----------------
// 128 blocks x 64 threads. Every thread simultaneously advances:
//   chain0: closed 8x8 system row r0 = tid>>3, col m  (redundant per block, feeds sA/sF)
//   chain1: batch row j = gid>>3, col m               (stores g_attn/g_ffn)
// Both chains add the same per-stage const vectors sA[t][m][.], sF[t][m][.].
__global__ void k_phaseB(const float* __restrict__ x,
                         const float* __restrict__ proj_w, const float* __restrict__ proj_b,
                         const float* __restrict__ rx, const float* __restrict__ ry,
                         const float* __restrict__ ffn_w, const float* __restrict__ ffn_b,
                         const float* __restrict__ ln1_g, const float* __restrict__ ln1_b,
                         const float* __restrict__ ln2_g, const float* __restrict__ ln2_b) {
    __shared__ float sRx[NB * 8], sRy[NB * 8];
    __shared__ float sFw[NB * 64], sFb[NB * 8];
    __shared__ float sL1G[NB * 8], sL1B[NB * 8], sL2G[NB * 8], sL2B[NB * 8];
    __shared__ float sPW[8], sPB[8];
    __shared__ float sA[NB][8][9];   // attn of rows 0..7 per stage (padded)
    __shared__ float sF[NB][8][9];   // ffn  of rows 0..7 per stage

    int tid = threadIdx.x;           // 0..63
    if (tid < NB * 8) {
        sRx[tid] = rx[tid]; sRy[tid] = ry[tid]; sFb[tid] = ffn_b[tid];
        sL1G[tid] = ln1_g[tid]; sL1B[tid] = ln1_b[tid];
        sL2G[tid] = ln2_g[tid]; sL2B[tid] = ln2_b[tid];
    }
    if (tid < 8) { sPW[tid] = proj_w[tid]; sPB[tid] = proj_b[tid]; }
    for (int u = tid; u < NB * 64; u += 64) sFw[u] = ffn_w[u];
    __syncthreads();

    int lane = tid & 31;
    int rowbase = lane & 24;
    const unsigned mask = 0xFFFFFFFFu;

    int r0 = tid >> 3;                        // closed-system row 0..7
    int m = tid & 7;                          // column 0..7 (shared by both chains)
    int gid = blockIdx.x * 64 + tid;
    int j = gid >> 3;                         // batch row 0..1023

    // gram + h init for both chains
    float pm[16];
    {
        float t16[16];
        psi16(x, m, t16);
#pragma unroll
        for (int u = 0; u < 16; u++) pm[u] = t16[fwd4(u)];
    }
    float h0[8], h1[8];
    {
        float pj[16];
        psi16(x, r0, pj);
        float d = 0.f;
#pragma unroll
        for (int u = 0; u < 16; u++) d += pj[u] * pm[u];
        float gr = fabsf(d);
#pragma unroll
        for (int k = 0; k < 8; k++) h0[k] = gr * sPW[k] + sPB[k];
    }
    {
        float pj[16];
        psi16(x, j, pj);
        float d = 0.f;
#pragma unroll
        for (int u = 0; u < 16; u++) d += pj[u] * pm[u];
        float gr = fabsf(d);
#pragma unroll
        for (int k = 0; k < 8; k++) h1[k] = gr * sPW[k] + sPB[k];

        // thread m==0 publishes psi_j / permuted psi_j for k_final
        if (m == 0) {
            float pp[16];
#pragma unroll
            for (int u = 0; u < 16; u++) pp[u] = pj[fwd4(u)];
            float4* po = (float4*)(g_psi + (size_t)j * 16);
            float4* pq = (float4*)(g_psip + (size_t)j * 16);
#pragma unroll
            for (int q = 0; q < 4; q++) {
                po[q] = make_float4(pj[4 * q], pj[4 * q + 1], pj[4 * q + 2], pj[4 * q + 3]);
                pq[q] = make_float4(pp[4 * q], pp[4 * q + 1], pp[4 * q + 2], pp[4 * q + 3]);
            }
        }
    }

    // hoist per-(t,m) constants off the chain
    float cRx[NB], ryv[NB];
#pragma unroll
    for (int t = 0; t < NB; t++) { cRx[t] = __cosf(rx[t * 8 + m]); ryv[t] = ry[t * 8 + m]; }

#pragma unroll
    for (int t = 0; t < NB; t++) {
        // ---- attn z's for both chains ----
        float z0 = cRx[t] * __cosf(h0[0]);
        float z1 = cRx[t] * __cosf(h1[0]);
        float zz0[8], zz1[8];
#pragma unroll
        for (int u = 0; u < 8; u++) {
            zz0[u] = __shfl_sync(mask, z0, rowbase | u);
            zz1[u] = __shfl_sync(mask, z1, rowbase | u);
        }
        float a0[8], a1[8];
        attn8(zz0, a0);
        attn8(zz1, a1);
        sA[t][r0][m] = a0[m];
        g_attn[(size_t)t * BATCH * 8 + (size_t)j * 8 + m] = a1[m];
        __syncthreads();

        // ---- LN1 (+shared const vector) ----
        float av[8];
#pragma unroll
        for (int k = 0; k < 8; k++) av[k] = sA[t][m][k];
#pragma unroll
        for (int k = 0; k < 8; k++) { h0[k] += av[k]; h1[k] += av[k]; }
        ln8(h0, sL1G + t * 8, sL1B + t * 8);
        ln8(h1, sL1G + t * 8, sL1B + t * 8);

        // ---- meas + own ffn component for both chains ----
        float mv0 = __cosf(h0[0] + ryv[t]); mv0 = mv0 > 0.f ? mv0 : 0.f;
        float mv1 = __cosf(h1[0] + ryv[t]); mv1 = mv1 > 0.f ? mv1 : 0.f;
        float s0 = sFb[t * 8 + m], s1 = s0;
#pragma unroll
        for (int u = 0; u < 8; u++) {
            float w = sFw[t * 64 + m * 8 + u];
            s0 += __shfl_sync(mask, mv0, rowbase | u) * w;
            s1 += __shfl_sync(mask, mv1, rowbase | u) * w;
        }
        sF[t][r0][m] = s0;
        g_ffn[(size_t)t * BATCH * 8 + (size_t)j * 8 + m] = s1;
        __syncthreads();

        // ---- LN2 (+shared const vector) ----
        float fv[8];
#pragma unroll
        for (int k = 0; k < 8; k++) fv[k] = sF[t][m][k];
#pragma unroll
        for (int k = 0; k < 8; k++) { h0[k] += fv[k]; h1[k] += fv[k]; }
        ln8(h0, sL2G + t * 8, sL2B + t * 8);
        ln8(h1, sL2G + t * 8, sL2B + t * 8);
    }
}

// ---------------- Final sweep: 1024x1024 elements, h never materialized ----------------
__global__ void k_final(const float* __restrict__ proj_w, const float* __restrict__ proj_b,
                        const float* __restrict__ ln1_g, const float* __restrict__ ln1_b,
                        const float* __restrict__ ln2_g, const float* __restrict__ ln2_b) {
    __shared__ float sPsiP[64][16];
    __shared__ float sAttn[NB][64][8];
    __shared__ float sFfn[NB][64][8];
    __shared__ float sPW[8], sPB[8];
    __shared__ float sL1G[NB][8], sL1B[NB][8], sL2G[NB][8], sL2B[NB][8];
    __shared__ float sRed[8][32][8];

    int jb = blockIdx.x;            // 16 j-blocks of 64 columns
    int ib = blockIdx.y;            // 32 i-blocks of 32 rows
    int tid = threadIdx.x;          // 256 threads = 8 warps
    int lane = tid & 31, w = tid >> 5;
    int j0 = jb * 64;
    int i = ib * 32 + lane;

    for (int u = tid; u < 64 * 16; u += 256) sPsiP[u >> 4][u & 15] = g_psip[j0 * 16 + u];
    for (int u = tid; u < NB * 64 * 8; u += 256) {
        int t = u >> 9; int r = u & 511;
        sAttn[t][r >> 3][r & 7] = g_attn[(size_t)t * BATCH * 8 + j0 * 8 + r];
        sFfn[t][r >> 3][r & 7] = g_ffn[(size_t)t * BATCH * 8 + j0 * 8 + r];
    }
    if (tid < 8) { sPW[tid] = proj_w[tid]; sPB[tid] = proj_b[tid]; }
    if (tid < NB * 8) {
        sL1G[tid >> 3][tid & 7] = ln1_g[tid];
        sL1B[tid >> 3][tid & 7] = ln1_b[tid];
        sL2G[tid >> 3][tid & 7] = ln2_g[tid];
        sL2B[tid >> 3][tid & 7] = ln2_b[tid];
    }
    __syncthreads();

    float psi[16];
    const float4* pp = (const float4*)(g_psi + (size_t)i * 16);
#pragma unroll
    for (int q = 0; q < 4; q++) {
        float4 v = pp[q];
        psi[4 * q] = v.x; psi[4 * q + 1] = v.y; psi[4 * q + 2] = v.z; psi[4 * q + 3] = v.w;
    }

    float acc[8];
#pragma unroll
    for (int k = 0; k < 8; k++) acc[k] = 0.f;

#pragma unroll 2
    for (int jj = 0; jj < 8; jj++) {
        int jc = w * 8 + jj;        // warp-uniform -> LDS broadcasts
        float d = 0.f;
#pragma unroll
        for (int u = 0; u < 16; u++) d += psi[u] * sPsiP[jc][u];
        float g = fabsf(d);
        float h[8];
#pragma unroll
        for (int k = 0; k < 8; k++) h[k] = g * sPW[k] + sPB[k];
#pragma unroll
        for (int t = 0; t < NB; t++) {
#pragma unroll
            for (int k = 0; k < 8; k++) h[k] += sAttn[t][jc][k];
            ln8(h, sL1G[t], sL1B[t]);
#pragma unroll
            for (int k = 0; k < 8; k++) h[k] += sFfn[t][jc][k];
            ln8(h, sL2G[t], sL2B[t]);
        }
#pragma unroll
        for (int k = 0; k < 8; k++) acc[k] += h[k];
    }

#pragma unroll
    for (int k = 0; k < 8; k++) sRed[w][lane][k] = acc[k];
    __syncthreads();
    {
        int il = tid >> 3, k = tid & 7;     // 256 threads = 32 rows x 8 channels
        float s = 0.f;
#pragma unroll
        for (int ww = 0; ww < 8; ww++) s += sRed[ww][il][k];
        g_part[(size_t)jb * BATCH * 8 + (size_t)(ib * 32 + il) * 8 + k] = s;
    }
}

__global__ void k_reduce(const float* __restrict__ cls_w, const float* __restrict__ cls_b,
                         float* __restrict__ out) {
    int i = blockIdx.x * blockDim.x + threadIdx.x;
    if (i >= BATCH) return;
    float p[8];
#pragma unroll
    for (int k = 0; k < 8; k++) p[k] = 0.f;
    for (int jb = 0; jb < 16; jb++) {
        const float4* q = (const float4*)(g_part + (size_t)jb * BATCH * 8 + (size_t)i * 8);
        float4 v0 = q[0], v1 = q[1];
        p[0] += v0.x; p[1] += v0.y; p[2] += v0.z; p[3] += v0.w;
        p[4] += v1.x; p[5] += v1.y; p[6] += v1.z; p[7] += v1.w;
    }
#pragma unroll
    for (int k = 0; k < 8; k++) p[k] *= (1.0f / BATCH);
#pragma unroll
    for (int c = 0; c < 10; c++) {
        float s = cls_b[c];
#pragma unroll
        for (int k = 0; k < 8; k++) s += p[k] * cls_w[c * 8 + k];
        out[i * 10 + c] = s;
    }
}

extern "C" void kernel_launch(void* const* d_in, const int* in_sizes, int n_in,
                              void* d_out, int out_size) {
    const float* x      = (const float*)d_in[0];
    const float* proj_w = (const float*)d_in[1];
    const float* proj_b = (const float*)d_in[2];
    const float* rx     = (const float*)d_in[3];
    const float* ry     = (const float*)d_in[4];
    const float* ffn_w  = (const float*)d_in[5];
    const float* ffn_b  = (const float*)d_in[6];
    const float* ln1_g  = (const float*)d_in[7];
    const float* ln1_b  = (const float*)d_in[8];
    const float* ln2_g  = (const float*)d_in[9];
    const float* ln2_b  = (const float*)d_in[10];
    const float* cls_w  = (const float*)d_in[11];
    const float* cls_b  = (const float*)d_in[12];
    float* out = (float*)d_out;

    k_phaseB<<<128, 64>>>(x, proj_w, proj_b, rx, ry, ffn_w, ffn_b,
                          ln1_g, ln1_b, ln2_g, ln2_b);
    k_final<<<dim3(16, 32), 256>>>(proj_w, proj_b, ln1_g, ln1_b, ln2_g, ln2_b);
    k_reduce<<<16, 64>>>(cls_w, cls_b, out);
}

// round 6
// speedup vs baseline: 2.6065x; 1.0756x over previous
#include <cuda_runtime.h>

#define NB 4
#define BATCH 1024
#define EPS 1e-5f

// Scratch (no allocations allowed). 16B-aligned for vectorized access.
__device__ __align__(16) float g_psi[BATCH * 16];
__device__ __align__(16) float g_psip[BATCH * 16];
__device__ __align__(16) float g_attn[NB * BATCH * 8];   // [t][j][k]
__device__ __align__(16) float g_ffn[NB * BATCH * 8];    // [t][j][k]
__device__ __align__(16) float g_part[16 * BATCH * 8];   // [jblock][i][k]

// ---------------- packed f32x2 helpers ----------------
typedef unsigned long long u64;
__device__ __forceinline__ u64 pk(float lo, float hi) {
    u64 r; asm("mov.b64 %0,{%1,%2};" : "=l"(r) : "f"(lo), "f"(hi)); return r;
}
__device__ __forceinline__ void up(u64 v, float& lo, float& hi) {
    asm("mov.b64 {%0,%1},%2;" : "=f"(lo), "=f"(hi) : "l"(v));
}
__device__ __forceinline__ u64 add2(u64 a, u64 b) {
    u64 r; asm("add.rn.f32x2 %0,%1,%2;" : "=l"(r) : "l"(a), "l"(b)); return r;
}
__device__ __forceinline__ u64 mul2(u64 a, u64 b) {
    u64 r; asm("mul.rn.f32x2 %0,%1,%2;" : "=l"(r) : "l"(a), "l"(b)); return r;
}
__device__ __forceinline__ u64 fma2(u64 a, u64 b, u64 c) {
    u64 r; asm("fma.rn.f32x2 %0,%1,%2,%3;" : "=l"(r) : "l"(a), "l"(b), "l"(c)); return r;
}

// Forward CNOT-ladder permutation for n=4: (0,1),(1,2),(2,3),(3,0)
__device__ __forceinline__ int fwd4(int m) {
    int idx = m;
    idx ^= ((idx >> 3) & 1) << 2;
    idx ^= ((idx >> 2) & 1) << 1;
    idx ^= ((idx >> 1) & 1) << 0;
    idx ^= ((idx >> 0) & 1) << 3;
    return idx;
}

// LayerNorm over 8 channels, tree-structured reductions (log-depth latency)
__device__ __forceinline__ void ln8(float h[8], const float* g, const float* b) {
    float m = ((h[0] + h[1]) + (h[2] + h[3])) + ((h[4] + h[5]) + (h[6] + h[7]));
    m *= 0.125f;
    float d0 = h[0] - m, d1 = h[1] - m, d2 = h[2] - m, d3 = h[3] - m;
    float d4 = h[4] - m, d5 = h[5] - m, d6 = h[6] - m, d7 = h[7] - m;
    float v = ((d0 * d0 + d1 * d1) + (d2 * d2 + d3 * d3)) +
              ((d4 * d4 + d5 * d5) + (d6 * d6 + d7 * d7));
    float rs = rsqrtf(v * 0.125f + EPS);
    h[0] = d0 * rs * g[0] + b[0]; h[1] = d1 * rs * g[1] + b[1];
    h[2] = d2 * rs * g[2] + b[2]; h[3] = d3 * rs * g[3] + b[3];
    h[4] = d4 * rs * g[4] + b[4]; h[5] = d5 * rs * g[5] + b[5];
    h[6] = d6 * rs * g[6] + b[6]; h[7] = d7 * rs * g[7] + b[7];
}

// Packed LN: out = h*G + (b - m*G), G = rs*g, var = E[h^2] - m^2 (same algebra, fewer ops)
__device__ __forceinline__ void ln8p(u64 h[4], const u64* g, const u64* b) {
    u64 s = add2(add2(h[0], h[1]), add2(h[2], h[3]));
    u64 q = mul2(h[0], h[0]);
    q = fma2(h[1], h[1], q);
    q = fma2(h[2], h[2], q);
    q = fma2(h[3], h[3], q);
    float sl, sh, ql, qh;
    up(s, sl, sh); up(q, ql, qh);
    float m = (sl + sh) * 0.125f;
    float e2 = (ql + qh) * 0.125f;
    float rs = rsqrtf(fmaf(-m, m, e2) + EPS);
    u64 rr = pk(rs, rs), nm = pk(-m, -m);
#pragma unroll
    for (int k = 0; k < 4; k++) {
        u64 G = mul2(rr, g[k]);
        u64 C = fma2(nm, G, b[k]);
        h[k] = fma2(h[k], G, C);
    }
}

// attn[w>=1] = z0*...*zw ; attn[0] = z1*...*z7
__device__ __forceinline__ void attn8(const float z[8], float a[8]) {
    float p = z[0];
#pragma unroll
    for (int w = 1; w < 8; w++) { p *= z[w]; a[w] = p; }
    float q = z[1];
#pragma unroll
    for (int w = 2; w < 8; w++) q *= z[w];
    a[0] = q;
}

__device__ __forceinline__ void psi16(const float* __restrict__ x, int row, float p[16]) {
    float c[4], s[4];
#pragma unroll
    for (int w = 0; w < 4; w++) {
        float hh = 0.5f * x[row * 4 + w];
        c[w] = __cosf(hh); s[w] = __sinf(hh);
    }
#pragma unroll
    for (int m = 0; m < 16; m++) {
        p[m] = (((m >> 3) & 1) ? s[0] : c[0]) * (((m >> 2) & 1) ? s[1] : c[1]) *
               (((m >> 1) & 1) ? s[2] : c[2]) * (((m >> 0) & 1) ? s[3] : c[3]);
    }
}

// ---------------- Fused sequential phase, interleaved (unchanged from R5) ----------------
__global__ void k_phaseB(const float* __restrict__ x,
                         const float* __restrict__ proj_w, const float* __restrict__ proj_b,
                         const float* __restrict__ rx, const float* __restrict__ ry,
                         const float* __restrict__ ffn_w, const float* __restrict__ ffn_b,
                         const float* __restrict__ ln1_g, const float* __restrict__ ln1_b,
                         const float* __restrict__ ln2_g, const float* __restrict__ ln2_b) {
    __shared__ float sRx[NB * 8], sRy[NB * 8];
    __shared__ float sFw[NB * 64], sFb[NB * 8];
    __shared__ float sL1G[NB * 8], sL1B[NB * 8], sL2G[NB * 8], sL2B[NB * 8];
    __shared__ float sPW[8], sPB[8];
    __shared__ float sA[NB][8][9];
    __shared__ float sF[NB][8][9];

    int tid = threadIdx.x;           // 0..63
    if (tid < NB * 8) {
        sRx[tid] = rx[tid]; sRy[tid] = ry[tid]; sFb[tid] = ffn_b[tid];
        sL1G[tid] = ln1_g[tid]; sL1B[tid] = ln1_b[tid];
        sL2G[tid] = ln2_g[tid]; sL2B[tid] = ln2_b[tid];
    }
    if (tid < 8) { sPW[tid] = proj_w[tid]; sPB[tid] = proj_b[tid]; }
    for (int u = tid; u < NB * 64; u += 64) sFw[u] = ffn_w[u];
    __syncthreads();

    int lane = tid & 31;
    int rowbase = lane & 24;
    const unsigned mask = 0xFFFFFFFFu;

    int r0 = tid >> 3;
    int m = tid & 7;
    int gid = blockIdx.x * 64 + tid;
    int j = gid >> 3;

    float pm[16];
    {
        float t16[16];
        psi16(x, m, t16);
#pragma unroll
        for (int u = 0; u < 16; u++) pm[u] = t16[fwd4(u)];
    }
    float h0[8], h1[8];
    {
        float pj[16];
        psi16(x, r0, pj);
        float d = 0.f;
#pragma unroll
        for (int u = 0; u < 16; u++) d += pj[u] * pm[u];
        float gr = fabsf(d);
#pragma unroll
        for (int k = 0; k < 8; k++) h0[k] = gr * sPW[k] + sPB[k];
    }
    {
        float pj[16];
        psi16(x, j, pj);
        float d = 0.f;
#pragma unroll
        for (int u = 0; u < 16; u++) d += pj[u] * pm[u];
        float gr = fabsf(d);
#pragma unroll
        for (int k = 0; k < 8; k++) h1[k] = gr * sPW[k] + sPB[k];

        if (m == 0) {
            float pp[16];
#pragma unroll
            for (int u = 0; u < 16; u++) pp[u] = pj[fwd4(u)];
            float4* po = (float4*)(g_psi + (size_t)j * 16);
            float4* pq = (float4*)(g_psip + (size_t)j * 16);
#pragma unroll
            for (int q = 0; q < 4; q++) {
                po[q] = make_float4(pj[4 * q], pj[4 * q + 1], pj[4 * q + 2], pj[4 * q + 3]);
                pq[q] = make_float4(pp[4 * q], pp[4 * q + 1], pp[4 * q + 2], pp[4 * q + 3]);
            }
        }
    }

    float cRx[NB], ryv[NB];
#pragma unroll
    for (int t = 0; t < NB; t++) { cRx[t] = __cosf(rx[t * 8 + m]); ryv[t] = ry[t * 8 + m]; }

#pragma unroll
    for (int t = 0; t < NB; t++) {
        float z0 = cRx[t] * __cosf(h0[0]);
        float z1 = cRx[t] * __cosf(h1[0]);
        float zz0[8], zz1[8];
#pragma unroll
        for (int u = 0; u < 8; u++) {
            zz0[u] = __shfl_sync(mask, z0, rowbase | u);
            zz1[u] = __shfl_sync(mask, z1, rowbase | u);
        }
        float a0[8], a1[8];
        attn8(zz0, a0);
        attn8(zz1, a1);
        sA[t][r0][m] = a0[m];
        g_attn[(size_t)t * BATCH * 8 + (size_t)j * 8 + m] = a1[m];
        __syncthreads();

        float av[8];
#pragma unroll
        for (int k = 0; k < 8; k++) av[k] = sA[t][m][k];
#pragma unroll
        for (int k = 0; k < 8; k++) { h0[k] += av[k]; h1[k] += av[k]; }
        ln8(h0, sL1G + t * 8, sL1B + t * 8);
        ln8(h1, sL1G + t * 8, sL1B + t * 8);

        float mv0 = __cosf(h0[0] + ryv[t]); mv0 = mv0 > 0.f ? mv0 : 0.f;
        float mv1 = __cosf(h1[0] + ryv[t]); mv1 = mv1 > 0.f ? mv1 : 0.f;
        float s0 = sFb[t * 8 + m], s1 = s0;
#pragma unroll
        for (int u = 0; u < 8; u++) {
            float w = sFw[t * 64 + m * 8 + u];
            s0 += __shfl_sync(mask, mv0, rowbase | u) * w;
            s1 += __shfl_sync(mask, mv1, rowbase | u) * w;
        }
        sF[t][r0][m] = s0;
        g_ffn[(size_t)t * BATCH * 8 + (size_t)j * 8 + m] = s1;
        __syncthreads();

        float fv[8];
#pragma unroll
        for (int k = 0; k < 8; k++) fv[k] = sF[t][m][k];
#pragma unroll
        for (int k = 0; k < 8; k++) { h0[k] += fv[k]; h1[k] += fv[k]; }
        ln8(h0, sL2G + t * 8, sL2B + t * 8);
        ln8(h1, sL2G + t * 8, sL2B + t * 8);
    }
}

// ---------------- Final sweep: packed f32x2 arithmetic ----------------
__global__ void k_final(const float* __restrict__ proj_w, const float* __restrict__ proj_b,
                        const float* __restrict__ ln1_g, const float* __restrict__ ln1_b,
                        const float* __restrict__ ln2_g, const float* __restrict__ ln2_b) {
    __shared__ float2 sPsiP[64][8];       // permuted psi, packed pairs
    __shared__ float2 sAttn[NB][64][4];
    __shared__ float2 sFfn[NB][64][4];
    __shared__ float2 sPW[4], sPB[4];
    __shared__ float2 sL1G[NB][4], sL1B[NB][4], sL2G[NB][4], sL2B[NB][4];
    __shared__ float sRed[8][32][8];

    int jb = blockIdx.x;            // 16 j-blocks of 64 columns
    int ib = blockIdx.y;            // 32 i-blocks of 32 rows
    int tid = threadIdx.x;          // 256 threads = 8 warps
    int lane = tid & 31, w = tid >> 5;
    int j0 = jb * 64;
    int i = ib * 32 + lane;

    const float2* gpp = (const float2*)(g_psip + (size_t)j0 * 16);
    for (int u = tid; u < 64 * 8; u += 256) sPsiP[u >> 3][u & 7] = gpp[u];
    for (int u = tid; u < NB * 64 * 4; u += 256) {
        int t = u >> 8; int r = u & 255;
        sAttn[t][r >> 2][r & 3] = ((const float2*)(g_attn + (size_t)t * BATCH * 8 + j0 * 8))[r];
        sFfn[t][r >> 2][r & 3]  = ((const float2*)(g_ffn  + (size_t)t * BATCH * 8 + j0 * 8))[r];
    }
    if (tid < 4) { sPW[tid] = ((const float2*)proj_w)[tid]; sPB[tid] = ((const float2*)proj_b)[tid]; }
    if (tid < NB * 4) {
        int t = tid >> 2, k = tid & 3;
        sL1G[t][k] = ((const float2*)ln1_g)[tid];
        sL1B[t][k] = ((const float2*)ln1_b)[tid];
        sL2G[t][k] = ((const float2*)ln2_g)[tid];
        sL2B[t][k] = ((const float2*)ln2_b)[tid];
    }
    __syncthreads();

    u64 psi[8];
    {
        const float4* pp = (const float4*)(g_psi + (size_t)i * 16);
#pragma unroll
        for (int q = 0; q < 4; q++) {
            float4 v = pp[q];
            psi[2 * q] = pk(v.x, v.y);
            psi[2 * q + 1] = pk(v.z, v.w);
        }
    }

    u64 acc[4];
#pragma unroll
    for (int k = 0; k < 4; k++) acc[k] = 0ull;

#pragma unroll 2
    for (int jj = 0; jj < 8; jj++) {
        int jc = w * 8 + jj;        // warp-uniform -> LDS broadcasts
        const u64* qq = (const u64*)&sPsiP[jc][0];
        u64 dp = mul2(psi[0], qq[0]);
#pragma unroll
        for (int u = 1; u < 8; u++) dp = fma2(psi[u], qq[u], dp);
        float dl, dh;
        up(dp, dl, dh);
        float g = fabsf(dl + dh);
        u64 gg = pk(g, g);

        u64 h[4];
#pragma unroll
        for (int k = 0; k < 4; k++)
            h[k] = fma2(gg, ((const u64*)sPW)[k], ((const u64*)sPB)[k]);

#pragma unroll
        for (int t = 0; t < NB; t++) {
            const u64* ap = (const u64*)&sAttn[t][jc][0];
#pragma unroll
            for (int k = 0; k < 4; k++) h[k] = add2(h[k], ap[k]);
            ln8p(h, (const u64*)sL1G[t], (const u64*)sL1B[t]);
            const u64* fp = (const u64*)&sFfn[t][jc][0];
#pragma unroll
            for (int k = 0; k < 4; k++) h[k] = add2(h[k], fp[k]);
            ln8p(h, (const u64*)sL2G[t], (const u64*)sL2B[t]);
        }
#pragma unroll
        for (int k = 0; k < 4; k++) acc[k] = add2(acc[k], h[k]);
    }

#pragma unroll
    for (int k = 0; k < 4; k++)
        up(acc[k], sRed[w][lane][2 * k], sRed[w][lane][2 * k + 1]);
    __syncthreads();
    {
        int il = tid >> 3, k = tid & 7;     // 256 threads = 32 rows x 8 channels
        float s = 0.f;
#pragma unroll
        for (int ww = 0; ww < 8; ww++) s += sRed[ww][il][k];
        g_part[(size_t)jb * BATCH * 8 + (size_t)(ib * 32 + il) * 8 + k] = s;
    }
}

__global__ void k_reduce(const float* __restrict__ cls_w, const float* __restrict__ cls_b,
                         float* __restrict__ out) {
    int i = blockIdx.x * blockDim.x + threadIdx.x;
    if (i >= BATCH) return;
    float p[8];
#pragma unroll
    for (int k = 0; k < 8; k++) p[k] = 0.f;
    for (int jb = 0; jb < 16; jb++) {
        const float4* q = (const float4*)(g_part + (size_t)jb * BATCH * 8 + (size_t)i * 8);
        float4 v0 = q[0], v1 = q[1];
        p[0] += v0.x; p[1] += v0.y; p[2] += v0.z; p[3] += v0.w;
        p[4] += v1.x; p[5] += v1.y; p[6] += v1.z; p[7] += v1.w;
    }
#pragma unroll
    for (int k = 0; k < 8; k++) p[k] *= (1.0f / BATCH);
#pragma unroll
    for (int c = 0; c < 10; c++) {
        float s = cls_b[c];
#pragma unroll
        for (int k = 0; k < 8; k++) s += p[k] * cls_w[c * 8 + k];
        out[i * 10 + c] = s;
    }
}

extern "C" void kernel_launch(void* const* d_in, const int* in_sizes, int n_in,
                              void* d_out, int out_size) {
    const float* x      = (const float*)d_in[0];
    const float* proj_w = (const float*)d_in[1];
    const float* proj_b = (const float*)d_in[2];
    const float* rx     = (const float*)d_in[3];
    const float* ry     = (const float*)d_in[4];
    const float* ffn_w  = (const float*)d_in[5];
    const float* ffn_b  = (const float*)d_in[6];
    const float* ln1_g  = (const float*)d_in[7];
    const float* ln1_b  = (const float*)d_in[8];
    const float* ln2_g  = (const float*)d_in[9];
    const float* ln2_b  = (const float*)d_in[10];
    const float* cls_w  = (const float*)d_in[11];
    const float* cls_b  = (const float*)d_in[12];
    float* out = (float*)d_out;

    k_phaseB<<<128, 64>>>(x, proj_w, proj_b, rx, ry, ffn_w, ffn_b,
                          ln1_g, ln1_b, ln2_g, ln2_b);
    k_final<<<dim3(16, 32), 256>>>(proj_w, proj_b, ln1_g, ln1_b, ln2_g, ln2_b);
    k_reduce<<<16, 64>>>(cls_w, cls_b, out);
}

// round 7
// speedup vs baseline: 2.6647x; 1.0223x over previous
#include <cuda_runtime.h>

#define NB 4
#define BATCH 1024
#define EPS 1e-5f

// Scratch (no allocations allowed). 16B-aligned for vectorized access.
__device__ __align__(16) float g_psi[BATCH * 16];
__device__ __align__(16) float g_psip[BATCH * 16];
__device__ __align__(16) float g_attn[NB * BATCH * 8];   // [t][j][k]
__device__ __align__(16) float g_ffn[NB * BATCH * 8];    // [t][j][k]
__device__ __align__(16) float g_part[16 * BATCH * 8];   // [jblock][i][k]

// ---------------- packed f32x2 helpers ----------------
typedef unsigned long long u64;
__device__ __forceinline__ u64 pk(float lo, float hi) {
    u64 r; asm("mov.b64 %0,{%1,%2};" : "=l"(r) : "f"(lo), "f"(hi)); return r;
}
__device__ __forceinline__ void up(u64 v, float& lo, float& hi) {
    asm("mov.b64 {%0,%1},%2;" : "=f"(lo), "=f"(hi) : "l"(v));
}
__device__ __forceinline__ u64 add2(u64 a, u64 b) {
    u64 r; asm("add.rn.f32x2 %0,%1,%2;" : "=l"(r) : "l"(a), "l"(b)); return r;
}
__device__ __forceinline__ u64 mul2(u64 a, u64 b) {
    u64 r; asm("mul.rn.f32x2 %0,%1,%2;" : "=l"(r) : "l"(a), "l"(b)); return r;
}
__device__ __forceinline__ u64 fma2(u64 a, u64 b, u64 c) {
    u64 r; asm("fma.rn.f32x2 %0,%1,%2,%3;" : "=l"(r) : "l"(a), "l"(b), "l"(c)); return r;
}

// Forward CNOT-ladder permutation for n=4: (0,1),(1,2),(2,3),(3,0)
__device__ __forceinline__ int fwd4(int m) {
    int idx = m;
    idx ^= ((idx >> 3) & 1) << 2;
    idx ^= ((idx >> 2) & 1) << 1;
    idx ^= ((idx >> 1) & 1) << 0;
    idx ^= ((idx >> 0) & 1) << 3;
    return idx;
}

// LayerNorm over 8 channels, tree-structured reductions (log-depth latency)
__device__ __forceinline__ void ln8(float h[8], const float* g, const float* b) {
    float m = ((h[0] + h[1]) + (h[2] + h[3])) + ((h[4] + h[5]) + (h[6] + h[7]));
    m *= 0.125f;
    float d0 = h[0] - m, d1 = h[1] - m, d2 = h[2] - m, d3 = h[3] - m;
    float d4 = h[4] - m, d5 = h[5] - m, d6 = h[6] - m, d7 = h[7] - m;
    float v = ((d0 * d0 + d1 * d1) + (d2 * d2 + d3 * d3)) +
              ((d4 * d4 + d5 * d5) + (d6 * d6 + d7 * d7));
    float rs = rsqrtf(v * 0.125f + EPS);
    h[0] = d0 * rs * g[0] + b[0]; h[1] = d1 * rs * g[1] + b[1];
    h[2] = d2 * rs * g[2] + b[2]; h[3] = d3 * rs * g[3] + b[3];
    h[4] = d4 * rs * g[4] + b[4]; h[5] = d5 * rs * g[5] + b[5];
    h[6] = d6 * rs * g[6] + b[6]; h[7] = d7 * rs * g[7] + b[7];
}

// Packed LN applied to 4 independent columns; gamma/beta loaded ONCE for all 4.
__device__ __forceinline__ void ln8p4(u64 h[4][4], const u64* g, const u64* b) {
    u64 gr[4], br[4];
#pragma unroll
    for (int k = 0; k < 4; k++) { gr[k] = g[k]; br[k] = b[k]; }
    float m[4], rs[4];
#pragma unroll
    for (int q = 0; q < 4; q++) {
        u64 s = add2(add2(h[q][0], h[q][1]), add2(h[q][2], h[q][3]));
        u64 qs = mul2(h[q][0], h[q][0]);
        qs = fma2(h[q][1], h[q][1], qs);
        qs = fma2(h[q][2], h[q][2], qs);
        qs = fma2(h[q][3], h[q][3], qs);
        float sl, sh, ql, qh;
        up(s, sl, sh); up(qs, ql, qh);
        m[q] = (sl + sh) * 0.125f;
        float e2 = (ql + qh) * 0.125f;
        rs[q] = rsqrtf(fmaf(-m[q], m[q], e2) + EPS);
    }
#pragma unroll
    for (int q = 0; q < 4; q++) {
        u64 rr = pk(rs[q], rs[q]), nm = pk(-m[q], -m[q]);
#pragma unroll
        for (int k = 0; k < 4; k++) {
            u64 G = mul2(rr, gr[k]);
            u64 C = fma2(nm, G, br[k]);
            h[q][k] = fma2(h[q][k], G, C);
        }
    }
}

// attn[w>=1] = z0*...*zw ; attn[0] = z1*...*z7
__device__ __forceinline__ void attn8(const float z[8], float a[8]) {
    float p = z[0];
#pragma unroll
    for (int w = 1; w < 8; w++) { p *= z[w]; a[w] = p; }
    float q = z[1];
#pragma unroll
    for (int w = 2; w < 8; w++) q *= z[w];
    a[0] = q;
}

__device__ __forceinline__ void psi16(const float* __restrict__ x, int row, float p[16]) {
    float c[4], s[4];
#pragma unroll
    for (int w = 0; w < 4; w++) {
        float hh = 0.5f * x[row * 4 + w];
        c[w] = __cosf(hh); s[w] = __sinf(hh);
    }
#pragma unroll
    for (int m = 0; m < 16; m++) {
        p[m] = (((m >> 3) & 1) ? s[0] : c[0]) * (((m >> 2) & 1) ? s[1] : c[1]) *
               (((m >> 1) & 1) ? s[2] : c[2]) * (((m >> 0) & 1) ? s[3] : c[3]);
    }
}

// ---------------- Fused sequential phase, interleaved (unchanged) ----------------
__global__ void k_phaseB(const float* __restrict__ x,
                         const float* __restrict__ proj_w, const float* __restrict__ proj_b,
                         const float* __restrict__ rx, const float* __restrict__ ry,
                         const float* __restrict__ ffn_w, const float* __restrict__ ffn_b,
                         const float* __restrict__ ln1_g, const float* __restrict__ ln1_b,
                         const float* __restrict__ ln2_g, const float* __restrict__ ln2_b) {
    __shared__ float sRx[NB * 8], sRy[NB * 8];
    __shared__ float sFw[NB * 64], sFb[NB * 8];
    __shared__ float sL1G[NB * 8], sL1B[NB * 8], sL2G[NB * 8], sL2B[NB * 8];
    __shared__ float sPW[8], sPB[8];
    __shared__ float sA[NB][8][9];
    __shared__ float sF[NB][8][9];

    int tid = threadIdx.x;           // 0..63
    if (tid < NB * 8) {
        sRx[tid] = rx[tid]; sRy[tid] = ry[tid]; sFb[tid] = ffn_b[tid];
        sL1G[tid] = ln1_g[tid]; sL1B[tid] = ln1_b[tid];
        sL2G[tid] = ln2_g[tid]; sL2B[tid] = ln2_b[tid];
    }
    if (tid < 8) { sPW[tid] = proj_w[tid]; sPB[tid] = proj_b[tid]; }
    for (int u = tid; u < NB * 64; u += 64) sFw[u] = ffn_w[u];
    __syncthreads();

    int lane = tid & 31;
    int rowbase = lane & 24;
    const unsigned mask = 0xFFFFFFFFu;

    int r0 = tid >> 3;
    int m = tid & 7;
    int gid = blockIdx.x * 64 + tid;
    int j = gid >> 3;

    float pm[16];
    {
        float t16[16];
        psi16(x, m, t16);
#pragma unroll
        for (int u = 0; u < 16; u++) pm[u] = t16[fwd4(u)];
    }
    float h0[8], h1[8];
    {
        float pj[16];
        psi16(x, r0, pj);
        float d = 0.f;
#pragma unroll
        for (int u = 0; u < 16; u++) d += pj[u] * pm[u];
        float gr = fabsf(d);
#pragma unroll
        for (int k = 0; k < 8; k++) h0[k] = gr * sPW[k] + sPB[k];
    }
    {
        float pj[16];
        psi16(x, j, pj);
        float d = 0.f;
#pragma unroll
        for (int u = 0; u < 16; u++) d += pj[u] * pm[u];
        float gr = fabsf(d);
#pragma unroll
        for (int k = 0; k < 8; k++) h1[k] = gr * sPW[k] + sPB[k];

        if (m == 0) {
            float pp[16];
#pragma unroll
            for (int u = 0; u < 16; u++) pp[u] = pj[fwd4(u)];
            float4* po = (float4*)(g_psi + (size_t)j * 16);
            float4* pq = (float4*)(g_psip + (size_t)j * 16);
#pragma unroll
            for (int q = 0; q < 4; q++) {
                po[q] = make_float4(pj[4 * q], pj[4 * q + 1], pj[4 * q + 2], pj[4 * q + 3]);
                pq[q] = make_float4(pp[4 * q], pp[4 * q + 1], pp[4 * q + 2], pp[4 * q + 3]);
            }
        }
    }

    float cRx[NB], ryv[NB];
#pragma unroll
    for (int t = 0; t < NB; t++) { cRx[t] = __cosf(rx[t * 8 + m]); ryv[t] = ry[t * 8 + m]; }

#pragma unroll
    for (int t = 0; t < NB; t++) {
        float z0 = cRx[t] * __cosf(h0[0]);
        float z1 = cRx[t] * __cosf(h1[0]);
        float zz0[8], zz1[8];
#pragma unroll
        for (int u = 0; u < 8; u++) {
            zz0[u] = __shfl_sync(mask, z0, rowbase | u);
            zz1[u] = __shfl_sync(mask, z1, rowbase | u);
        }
        float a0[8], a1[8];
        attn8(zz0, a0);
        attn8(zz1, a1);
        sA[t][r0][m] = a0[m];
        g_attn[(size_t)t * BATCH * 8 + (size_t)j * 8 + m] = a1[m];
        __syncthreads();

        float av[8];
#pragma unroll
        for (int k = 0; k < 8; k++) av[k] = sA[t][m][k];
#pragma unroll
        for (int k = 0; k < 8; k++) { h0[k] += av[k]; h1[k] += av[k]; }
        ln8(h0, sL1G + t * 8, sL1B + t * 8);
        ln8(h1, sL1G + t * 8, sL1B + t * 8);

        float mv0 = __cosf(h0[0] + ryv[t]); mv0 = mv0 > 0.f ? mv0 : 0.f;
        float mv1 = __cosf(h1[0] + ryv[t]); mv1 = mv1 > 0.f ? mv1 : 0.f;
        float s0 = sFb[t * 8 + m], s1 = s0;
#pragma unroll
        for (int u = 0; u < 8; u++) {
            float w = sFw[t * 64 + m * 8 + u];
            s0 += __shfl_sync(mask, mv0, rowbase | u) * w;
            s1 += __shfl_sync(mask, mv1, rowbase | u) * w;
        }
        sF[t][r0][m] = s0;
        g_ffn[(size_t)t * BATCH * 8 + (size_t)j * 8 + m] = s1;
        __syncthreads();

        float fv[8];
#pragma unroll
        for (int k = 0; k < 8; k++) fv[k] = sF[t][m][k];
#pragma unroll
        for (int k = 0; k < 8; k++) { h0[k] += fv[k]; h1[k] += fv[k]; }
        ln8(h0, sL2G + t * 8, sL2B + t * 8);
        ln8(h1, sL2G + t * 8, sL2B + t * 8);
    }
}

// ---------------- Final sweep: packed f32x2, 4-column ILP, hoisted LN params ----------------
__global__ void __launch_bounds__(256) k_final(
                        const float* __restrict__ proj_w, const float* __restrict__ proj_b,
                        const float* __restrict__ ln1_g, const float* __restrict__ ln1_b,
                        const float* __restrict__ ln2_g, const float* __restrict__ ln2_b) {
    __shared__ float2 sPsiP[64][8];       // permuted psi, packed pairs
    __shared__ float2 sAttn[NB][64][4];
    __shared__ float2 sFfn[NB][64][4];
    __shared__ float2 sPW[4], sPB[4];
    __shared__ float2 sL1G[NB][4], sL1B[NB][4], sL2G[NB][4], sL2B[NB][4];
    __shared__ float sRed[8][32][8];

    int jb = blockIdx.x;            // 16 j-blocks of 64 columns
    int ib = blockIdx.y;            // 32 i-blocks of 32 rows
    int tid = threadIdx.x;          // 256 threads = 8 warps
    int lane = tid & 31, w = tid >> 5;
    int j0 = jb * 64;
    int i = ib * 32 + lane;

    const float2* gpp = (const float2*)(g_psip + (size_t)j0 * 16);
    for (int u = tid; u < 64 * 8; u += 256) sPsiP[u >> 3][u & 7] = gpp[u];
    for (int u = tid; u < NB * 64 * 4; u += 256) {
        int t = u >> 8; int r = u & 255;
        sAttn[t][r >> 2][r & 3] = ((const float2*)(g_attn + (size_t)t * BATCH * 8 + j0 * 8))[r];
        sFfn[t][r >> 2][r & 3]  = ((const float2*)(g_ffn  + (size_t)t * BATCH * 8 + j0 * 8))[r];
    }
    if (tid < 4) { sPW[tid] = ((const float2*)proj_w)[tid]; sPB[tid] = ((const float2*)proj_b)[tid]; }
    if (tid < NB * 4) {
        int t = tid >> 2, k = tid & 3;
        sL1G[t][k] = ((const float2*)ln1_g)[tid];
        sL1B[t][k] = ((const float2*)ln1_b)[tid];
        sL2G[t][k] = ((const float2*)ln2_g)[tid];
        sL2B[t][k] = ((const float2*)ln2_b)[tid];
    }
    __syncthreads();

    u64 psi[8];
    {
        const float4* pp = (const float4*)(g_psi + (size_t)i * 16);
#pragma unroll
        for (int q = 0; q < 4; q++) {
            float4 v = pp[q];
            psi[2 * q] = pk(v.x, v.y);
            psi[2 * q + 1] = pk(v.z, v.w);
        }
    }

    u64 acc[4];
#pragma unroll
    for (int k = 0; k < 4; k++) acc[k] = 0ull;

    u64 pw[4], pb[4];
#pragma unroll
    for (int k = 0; k < 4; k++) { pw[k] = ((const u64*)sPW)[k]; pb[k] = ((const u64*)sPB)[k]; }

#pragma unroll
    for (int pass = 0; pass < 2; pass++) {
        int jcb = w * 8 + pass * 4;         // warp-uniform base column
        u64 h[4][4];

        // gram dot + h init for 4 columns (independent chains)
#pragma unroll
        for (int q = 0; q < 4; q++) {
            const u64* qq = (const u64*)&sPsiP[jcb + q][0];
            u64 dp = mul2(psi[0], qq[0]);
#pragma unroll
            for (int u = 1; u < 8; u++) dp = fma2(psi[u], qq[u], dp);
            float dl, dh;
            up(dp, dl, dh);
            float g = fabsf(dl + dh);
            u64 gg = pk(g, g);
#pragma unroll
            for (int k = 0; k < 4; k++) h[q][k] = fma2(gg, pw[k], pb[k]);
        }

#pragma unroll
        for (int t = 0; t < NB; t++) {
#pragma unroll
            for (int q = 0; q < 4; q++) {
                const u64* ap = (const u64*)&sAttn[t][jcb + q][0];
#pragma unroll
                for (int k = 0; k < 4; k++) h[q][k] = add2(h[q][k], ap[k]);
            }
            ln8p4(h, (const u64*)sL1G[t], (const u64*)sL1B[t]);
#pragma unroll
            for (int q = 0; q < 4; q++) {
                const u64* fp = (const u64*)&sFfn[t][jcb + q][0];
#pragma unroll
                for (int k = 0; k < 4; k++) h[q][k] = add2(h[q][k], fp[k]);
            }
            ln8p4(h, (const u64*)sL2G[t], (const u64*)sL2B[t]);
        }

#pragma unroll
        for (int k = 0; k < 4; k++)
            acc[k] = add2(acc[k], add2(add2(h[0][k], h[1][k]), add2(h[2][k], h[3][k])));
    }

#pragma unroll
    for (int k = 0; k < 4; k++)
        up(acc[k], sRed[w][lane][2 * k], sRed[w][lane][2 * k + 1]);
    __syncthreads();
    {
        int il = tid >> 3, k = tid & 7;     // 256 threads = 32 rows x 8 channels
        float s = 0.f;
#pragma unroll
        for (int ww = 0; ww < 8; ww++) s += sRed[ww][il][k];
        g_part[(size_t)jb * BATCH * 8 + (size_t)(ib * 32 + il) * 8 + k] = s;
    }
}

__global__ void k_reduce(const float* __restrict__ cls_w, const float* __restrict__ cls_b,
                         float* __restrict__ out) {
    int i = blockIdx.x * blockDim.x + threadIdx.x;
    if (i >= BATCH) return;
    float p[8];
#pragma unroll
    for (int k = 0; k < 8; k++) p[k] = 0.f;
    for (int jb = 0; jb < 16; jb++) {
        const float4* q = (const float4*)(g_part + (size_t)jb * BATCH * 8 + (size_t)i * 8);
        float4 v0 = q[0], v1 = q[1];
        p[0] += v0.x; p[1] += v0.y; p[2] += v0.z; p[3] += v0.w;
        p[4] += v1.x; p[5] += v1.y; p[6] += v1.z; p[7] += v1.w;
    }
#pragma unroll
    for (int k = 0; k < 8; k++) p[k] *= (1.0f / BATCH);
#pragma unroll
    for (int c = 0; c < 10; c++) {
        float s = cls_b[c];
#pragma unroll
        for (int k = 0; k < 8; k++) s += p[k] * cls_w[c * 8 + k];
        out[i * 10 + c] = s;
    }
}

extern "C" void kernel_launch(void* const* d_in, const int* in_sizes, int n_in,
                              void* d_out, int out_size) {
    const float* x      = (const float*)d_in[0];
    const float* proj_w = (const float*)d_in[1];
    const float* proj_b = (const float*)d_in[2];
    const float* rx     = (const float*)d_in[3];
    const float* ry     = (const float*)d_in[4];
    const float* ffn_w  = (const float*)d_in[5];
    const float* ffn_b  = (const float*)d_in[6];
    const float* ln1_g  = (const float*)d_in[7];
    const float* ln1_b  = (const float*)d_in[8];
    const float* ln2_g  = (const float*)d_in[9];
    const float* ln2_b  = (const float*)d_in[10];
    const float* cls_w  = (const float*)d_in[11];
    const float* cls_b  = (const float*)d_in[12];
    float* out = (float*)d_out;

    k_phaseB<<<128, 64>>>(x, proj_w, proj_b, rx, ry, ffn_w, ffn_b,
                          ln1_g, ln1_b, ln2_g, ln2_b);
    k_final<<<dim3(16, 32), 256>>>(proj_w, proj_b, ln1_g, ln1_b, ln2_g, ln2_b);
    k_reduce<<<16, 64>>>(cls_w, cls_b, out);
}

// round 8
// speedup vs baseline: 2.8787x; 1.0803x over previous
#include <cuda_runtime.h>

#define NB 4
#define BATCH 1024
#define EPS 1e-5f

// Scratch (no allocations allowed). 16B-aligned for vectorized access.
__device__ __align__(16) float g_psi[BATCH * 16];
__device__ __align__(16) float g_psip[BATCH * 16];
__device__ __align__(16) float g_attn[NB * BATCH * 8];   // [t][j][k]
__device__ __align__(16) float g_ffn[NB * BATCH * 8];    // [t][j][k]

// ---------------- packed f32x2 helpers ----------------
typedef unsigned long long u64;
__device__ __forceinline__ u64 pk(float lo, float hi) {
    u64 r; asm("mov.b64 %0,{%1,%2};" : "=l"(r) : "f"(lo), "f"(hi)); return r;
}
__device__ __forceinline__ void up(u64 v, float& lo, float& hi) {
    asm("mov.b64 {%0,%1},%2;" : "=f"(lo), "=f"(hi) : "l"(v));
}
__device__ __forceinline__ u64 add2(u64 a, u64 b) {
    u64 r; asm("add.rn.f32x2 %0,%1,%2;" : "=l"(r) : "l"(a), "l"(b)); return r;
}
__device__ __forceinline__ u64 mul2(u64 a, u64 b) {
    u64 r; asm("mul.rn.f32x2 %0,%1,%2;" : "=l"(r) : "l"(a), "l"(b)); return r;
}
__device__ __forceinline__ u64 fma2(u64 a, u64 b, u64 c) {
    u64 r; asm("fma.rn.f32x2 %0,%1,%2,%3;" : "=l"(r) : "l"(a), "l"(b), "l"(c)); return r;
}

// Forward CNOT-ladder permutation for n=4: (0,1),(1,2),(2,3),(3,0)
__device__ __forceinline__ int fwd4(int m) {
    int idx = m;
    idx ^= ((idx >> 3) & 1) << 2;
    idx ^= ((idx >> 2) & 1) << 1;
    idx ^= ((idx >> 1) & 1) << 0;
    idx ^= ((idx >> 0) & 1) << 3;
    return idx;
}

// LayerNorm over 8 channels, tree-structured reductions (log-depth latency)
__device__ __forceinline__ void ln8(float h[8], const float* g, const float* b) {
    float m = ((h[0] + h[1]) + (h[2] + h[3])) + ((h[4] + h[5]) + (h[6] + h[7]));
    m *= 0.125f;
    float d0 = h[0] - m, d1 = h[1] - m, d2 = h[2] - m, d3 = h[3] - m;
    float d4 = h[4] - m, d5 = h[5] - m, d6 = h[6] - m, d7 = h[7] - m;
    float v = ((d0 * d0 + d1 * d1) + (d2 * d2 + d3 * d3)) +
              ((d4 * d4 + d5 * d5) + (d6 * d6 + d7 * d7));
    float rs = rsqrtf(v * 0.125f + EPS);
    h[0] = d0 * rs * g[0] + b[0]; h[1] = d1 * rs * g[1] + b[1];
    h[2] = d2 * rs * g[2] + b[2]; h[3] = d3 * rs * g[3] + b[3];
    h[4] = d4 * rs * g[4] + b[4]; h[5] = d5 * rs * g[5] + b[5];
    h[6] = d6 * rs * g[6] + b[6]; h[7] = d7 * rs * g[7] + b[7];
}

// Packed LN applied to 4 independent columns; gamma/beta loaded ONCE (LDS.128).
__device__ __forceinline__ void ln8p4(u64 h[4][4], const u64* g, const u64* b) {
    ulonglong2 g01 = *(const ulonglong2*)g;
    ulonglong2 g23 = *(const ulonglong2*)(g + 2);
    ulonglong2 b01 = *(const ulonglong2*)b;
    ulonglong2 b23 = *(const ulonglong2*)(b + 2);
    u64 gr[4] = { g01.x, g01.y, g23.x, g23.y };
    u64 br[4] = { b01.x, b01.y, b23.x, b23.y };
    float m[4], rs[4];
#pragma unroll
    for (int q = 0; q < 4; q++) {
        u64 s = add2(add2(h[q][0], h[q][1]), add2(h[q][2], h[q][3]));
        u64 qs = mul2(h[q][0], h[q][0]);
        qs = fma2(h[q][1], h[q][1], qs);
        qs = fma2(h[q][2], h[q][2], qs);
        qs = fma2(h[q][3], h[q][3], qs);
        float sl, sh, ql, qh;
        up(s, sl, sh); up(qs, ql, qh);
        m[q] = (sl + sh) * 0.125f;
        float e2 = (ql + qh) * 0.125f;
        rs[q] = rsqrtf(fmaf(-m[q], m[q], e2) + EPS);
    }
#pragma unroll
    for (int q = 0; q < 4; q++) {
        u64 rr = pk(rs[q], rs[q]), nm = pk(-m[q], -m[q]);
#pragma unroll
        for (int k = 0; k < 4; k++) {
            u64 G = mul2(rr, gr[k]);
            u64 C = fma2(nm, G, br[k]);
            h[q][k] = fma2(h[q][k], G, C);
        }
    }
}

// attn[w>=1] = z0*...*zw ; attn[0] = z1*...*z7
__device__ __forceinline__ void attn8(const float z[8], float a[8]) {
    float p = z[0];
#pragma unroll
    for (int w = 1; w < 8; w++) { p *= z[w]; a[w] = p; }
    float q = z[1];
#pragma unroll
    for (int w = 2; w < 8; w++) q *= z[w];
    a[0] = q;
}

__device__ __forceinline__ void psi16(const float* __restrict__ x, int row, float p[16]) {
    float c[4], s[4];
#pragma unroll
    for (int w = 0; w < 4; w++) {
        float hh = 0.5f * x[row * 4 + w];
        c[w] = __cosf(hh); s[w] = __sinf(hh);
    }
#pragma unroll
    for (int m = 0; m < 16; m++) {
        p[m] = (((m >> 3) & 1) ? s[0] : c[0]) * (((m >> 2) & 1) ? s[1] : c[1]) *
               (((m >> 1) & 1) ? s[2] : c[2]) * (((m >> 0) & 1) ? s[3] : c[3]);
    }
}

// ---------------- Fused sequential phase (also initializes out = cls_b) ----------------
__global__ void k_phaseB(const float* __restrict__ x,
                         const float* __restrict__ proj_w, const float* __restrict__ proj_b,
                         const float* __restrict__ rx, const float* __restrict__ ry,
                         const float* __restrict__ ffn_w, const float* __restrict__ ffn_b,
                         const float* __restrict__ ln1_g, const float* __restrict__ ln1_b,
                         const float* __restrict__ ln2_g, const float* __restrict__ ln2_b,
                         const float* __restrict__ cls_b, float* __restrict__ out) {
    __shared__ float sRx[NB * 8], sRy[NB * 8];
    __shared__ float sFw[NB * 64], sFb[NB * 8];
    __shared__ float sL1G[NB * 8], sL1B[NB * 8], sL2G[NB * 8], sL2B[NB * 8];
    __shared__ float sPW[8], sPB[8];
    __shared__ float sA[NB][8][9];
    __shared__ float sF[NB][8][9];

    int tid = threadIdx.x;           // 0..63
    int gid = blockIdx.x * 64 + tid;

    // initialize classifier output with bias (k_final atomically accumulates onto it)
    for (int u = gid; u < BATCH * 10; u += 128 * 64) out[u] = cls_b[u % 10];

    if (tid < NB * 8) {
        sRx[tid] = rx[tid]; sRy[tid] = ry[tid]; sFb[tid] = ffn_b[tid];
        sL1G[tid] = ln1_g[tid]; sL1B[tid] = ln1_b[tid];
        sL2G[tid] = ln2_g[tid]; sL2B[tid] = ln2_b[tid];
    }
    if (tid < 8) { sPW[tid] = proj_w[tid]; sPB[tid] = proj_b[tid]; }
    for (int u = tid; u < NB * 64; u += 64) sFw[u] = ffn_w[u];
    __syncthreads();

    int lane = tid & 31;
    int rowbase = lane & 24;
    const unsigned mask = 0xFFFFFFFFu;

    int r0 = tid >> 3;
    int m = tid & 7;
    int j = gid >> 3;

    float pm[16];
    {
        float t16[16];
        psi16(x, m, t16);
#pragma unroll
        for (int u = 0; u < 16; u++) pm[u] = t16[fwd4(u)];
    }
    float h0[8], h1[8];
    {
        float pj[16];
        psi16(x, r0, pj);
        float d = 0.f;
#pragma unroll
        for (int u = 0; u < 16; u++) d += pj[u] * pm[u];
        float gr = fabsf(d);
#pragma unroll
        for (int k = 0; k < 8; k++) h0[k] = gr * sPW[k] + sPB[k];
    }
    {
        float pj[16];
        psi16(x, j, pj);
        float d = 0.f;
#pragma unroll
        for (int u = 0; u < 16; u++) d += pj[u] * pm[u];
        float gr = fabsf(d);
#pragma unroll
        for (int k = 0; k < 8; k++) h1[k] = gr * sPW[k] + sPB[k];

        if (m == 0) {
            float pp[16];
#pragma unroll
            for (int u = 0; u < 16; u++) pp[u] = pj[fwd4(u)];
            float4* po = (float4*)(g_psi + (size_t)j * 16);
            float4* pq = (float4*)(g_psip + (size_t)j * 16);
#pragma unroll
            for (int q = 0; q < 4; q++) {
                po[q] = make_float4(pj[4 * q], pj[4 * q + 1], pj[4 * q + 2], pj[4 * q + 3]);
                pq[q] = make_float4(pp[4 * q], pp[4 * q + 1], pp[4 * q + 2], pp[4 * q + 3]);
            }
        }
    }

    float cRx[NB], ryv[NB];
#pragma unroll
    for (int t = 0; t < NB; t++) { cRx[t] = __cosf(rx[t * 8 + m]); ryv[t] = ry[t * 8 + m]; }

#pragma unroll
    for (int t = 0; t < NB; t++) {
        float z0 = cRx[t] * __cosf(h0[0]);
        float z1 = cRx[t] * __cosf(h1[0]);
        float zz0[8], zz1[8];
#pragma unroll
        for (int u = 0; u < 8; u++) {
            zz0[u] = __shfl_sync(mask, z0, rowbase | u);
            zz1[u] = __shfl_sync(mask, z1, rowbase | u);
        }
        float a0[8], a1[8];
        attn8(zz0, a0);
        attn8(zz1, a1);
        sA[t][r0][m] = a0[m];
        g_attn[(size_t)t * BATCH * 8 + (size_t)j * 8 + m] = a1[m];
        __syncthreads();

        float av[8];
#pragma unroll
        for (int k = 0; k < 8; k++) av[k] = sA[t][m][k];
#pragma unroll
        for (int k = 0; k < 8; k++) { h0[k] += av[k]; h1[k] += av[k]; }
        ln8(h0, sL1G + t * 8, sL1B + t * 8);
        ln8(h1, sL1G + t * 8, sL1B + t * 8);

        float mv0 = __cosf(h0[0] + ryv[t]); mv0 = mv0 > 0.f ? mv0 : 0.f;
        float mv1 = __cosf(h1[0] + ryv[t]); mv1 = mv1 > 0.f ? mv1 : 0.f;
        float s0 = sFb[t * 8 + m], s1 = s0;
#pragma unroll
        for (int u = 0; u < 8; u++) {
            float w = sFw[t * 64 + m * 8 + u];
            s0 += __shfl_sync(mask, mv0, rowbase | u) * w;
            s1 += __shfl_sync(mask, mv1, rowbase | u) * w;
        }
        sF[t][r0][m] = s0;
        g_ffn[(size_t)t * BATCH * 8 + (size_t)j * 8 + m] = s1;
        __syncthreads();

        float fv[8];
#pragma unroll
        for (int k = 0; k < 8; k++) fv[k] = sF[t][m][k];
#pragma unroll
        for (int k = 0; k < 8; k++) { h0[k] += fv[k]; h1[k] += fv[k]; }
        ln8(h0, sL2G + t * 8, sL2B + t * 8);
        ln8(h1, sL2G + t * 8, sL2B + t * 8);
    }
}

// ---------------- Final sweep: LDS.128 everywhere, 3 blocks/SM, fused classifier ----------------
__global__ void __launch_bounds__(256, 3) k_final(
                        const float* __restrict__ proj_w, const float* __restrict__ proj_b,
                        const float* __restrict__ ln1_g, const float* __restrict__ ln1_b,
                        const float* __restrict__ ln2_g, const float* __restrict__ ln2_b,
                        const float* __restrict__ cls_w, float* __restrict__ out) {
    __shared__ __align__(16) u64 sPsiP[64][8];       // permuted psi, packed pairs
    __shared__ __align__(16) u64 sAttn[NB][64][4];
    __shared__ __align__(16) u64 sFfn[NB][64][4];
    __shared__ __align__(16) u64 sPW[4], sPB[4];
    __shared__ __align__(16) u64 sL1G[NB][4], sL1B[NB][4], sL2G[NB][4], sL2B[NB][4];
    __shared__ float sClsW[10][8];
    __shared__ float sRed[8][32][8];

    int jb = blockIdx.x;            // 16 j-blocks of 64 columns
    int ib = blockIdx.y;            // 32 i-blocks of 32 rows
    int tid = threadIdx.x;          // 256 threads = 8 warps
    int lane = tid & 31, w = tid >> 5;
    int j0 = jb * 64;
    int i = ib * 32 + lane;

    // cooperative 128-bit tile loads
    {
        const ulonglong2* gp = (const ulonglong2*)(g_psip + (size_t)j0 * 16);
        ((ulonglong2*)sPsiP)[tid] = gp[tid];                       // 256 x 16B = psip tile
        for (int u = tid; u < NB * 128; u += 256) {
            int t = u >> 7, r = u & 127;
            ((ulonglong2*)&sAttn[t][0][0])[r] =
                ((const ulonglong2*)(g_attn + (size_t)t * BATCH * 8 + j0 * 8))[r];
            ((ulonglong2*)&sFfn[t][0][0])[r] =
                ((const ulonglong2*)(g_ffn + (size_t)t * BATCH * 8 + j0 * 8))[r];
        }
    }
    if (tid < 4) { sPW[tid] = ((const u64*)proj_w)[tid]; sPB[tid] = ((const u64*)proj_b)[tid]; }
    if (tid < NB * 4) {
        int t = tid >> 2, k = tid & 3;
        sL1G[t][k] = ((const u64*)ln1_g)[tid];
        sL1B[t][k] = ((const u64*)ln1_b)[tid];
        sL2G[t][k] = ((const u64*)ln2_g)[tid];
        sL2B[t][k] = ((const u64*)ln2_b)[tid];
    }
    if (tid < 80) sClsW[tid >> 3][tid & 7] = cls_w[tid];
    __syncthreads();

    u64 psi[8];
    {
        const float4* pp = (const float4*)(g_psi + (size_t)i * 16);
#pragma unroll
        for (int q = 0; q < 4; q++) {
            float4 v = pp[q];
            psi[2 * q] = pk(v.x, v.y);
            psi[2 * q + 1] = pk(v.z, v.w);
        }
    }

    u64 acc[4];
#pragma unroll
    for (int k = 0; k < 4; k++) acc[k] = 0ull;

#pragma unroll
    for (int pass = 0; pass < 2; pass++) {
        int jcb = w * 8 + pass * 4;         // warp-uniform base column
        u64 h[4][4];

        // gram dot + h init for 4 columns (independent chains)
        {
            ulonglong2 pw01 = *(const ulonglong2*)&sPW[0];
            ulonglong2 pw23 = *(const ulonglong2*)&sPW[2];
            ulonglong2 pb01 = *(const ulonglong2*)&sPB[0];
            ulonglong2 pb23 = *(const ulonglong2*)&sPB[2];
#pragma unroll
            for (int q = 0; q < 4; q++) {
                const u64* qq = &sPsiP[jcb + q][0];
                ulonglong2 q0 = *(const ulonglong2*)qq;
                ulonglong2 q1 = *(const ulonglong2*)(qq + 2);
                ulonglong2 q2 = *(const ulonglong2*)(qq + 4);
                ulonglong2 q3 = *(const ulonglong2*)(qq + 6);
                u64 dp = mul2(psi[0], q0.x);
                dp = fma2(psi[1], q0.y, dp);
                dp = fma2(psi[2], q1.x, dp);
                dp = fma2(psi[3], q1.y, dp);
                dp = fma2(psi[4], q2.x, dp);
                dp = fma2(psi[5], q2.y, dp);
                dp = fma2(psi[6], q3.x, dp);
                dp = fma2(psi[7], q3.y, dp);
                float dl, dh;
                up(dp, dl, dh);
                float g = fabsf(dl + dh);
                u64 gg = pk(g, g);
                h[q][0] = fma2(gg, pw01.x, pb01.x);
                h[q][1] = fma2(gg, pw01.y, pb01.y);
                h[q][2] = fma2(gg, pw23.x, pb23.x);
                h[q][3] = fma2(gg, pw23.y, pb23.y);
            }
        }

#pragma unroll
        for (int t = 0; t < NB; t++) {
#pragma unroll
            for (int q = 0; q < 4; q++) {
                const u64* ap = &sAttn[t][jcb + q][0];
                ulonglong2 a01 = *(const ulonglong2*)ap;
                ulonglong2 a23 = *(const ulonglong2*)(ap + 2);
                h[q][0] = add2(h[q][0], a01.x);
                h[q][1] = add2(h[q][1], a01.y);
                h[q][2] = add2(h[q][2], a23.x);
                h[q][3] = add2(h[q][3], a23.y);
            }
            ln8p4(h, sL1G[t], sL1B[t]);
#pragma unroll
            for (int q = 0; q < 4; q++) {
                const u64* fp = &sFfn[t][jcb + q][0];
                ulonglong2 f01 = *(const ulonglong2*)fp;
                ulonglong2 f23 = *(const ulonglong2*)(fp + 2);
                h[q][0] = add2(h[q][0], f01.x);
                h[q][1] = add2(h[q][1], f01.y);
                h[q][2] = add2(h[q][2], f23.x);
                h[q][3] = add2(h[q][3], f23.y);
            }
            ln8p4(h, sL2G[t], sL2B[t]);
        }

#pragma unroll
        for (int k = 0; k < 4; k++)
            acc[k] = add2(acc[k], add2(add2(h[0][k], h[1][k]), add2(h[2][k], h[3][k])));
    }

#pragma unroll
    for (int k = 0; k < 4; k++)
        up(acc[k], sRed[w][lane][2 * k], sRed[w][lane][2 * k + 1]);
    __syncthreads();
    {
        int il = tid >> 3, k = tid & 7;     // 256 threads = 32 rows x 8 channels
        float s = 0.f;
#pragma unroll
        for (int ww = 0; ww < 8; ww++) s += sRed[ww][il][k];
        sRed[0][il][k] = s;                 // exclusive location per thread
    }
    __syncthreads();
    {
        int il = tid >> 3, c = tid & 7;     // classifier: rows x classes 0..7 (+8,9)
        int ii = ib * 32 + il;
        float d = 0.f;
#pragma unroll
        for (int k = 0; k < 8; k++) d += sRed[0][il][k] * sClsW[c][k];
        atomicAdd(&out[ii * 10 + c], d * (1.0f / BATCH));
        if (c < 2) {
            int c1 = c + 8;
            float d1 = 0.f;
#pragma unroll
            for (int k = 0; k < 8; k++) d1 += sRed[0][il][k] * sClsW[c1][k];
            atomicAdd(&out[ii * 10 + c1], d1 * (1.0f / BATCH));
        }
    }
}

extern "C" void kernel_launch(void* const* d_in, const int* in_sizes, int n_in,
                              void* d_out, int out_size) {
    const float* x      = (const float*)d_in[0];
    const float* proj_w = (const float*)d_in[1];
    const float* proj_b = (const float*)d_in[2];
    const float* rx     = (const float*)d_in[3];
    const float* ry     = (const float*)d_in[4];
    const float* ffn_w  = (const float*)d_in[5];
    const float* ffn_b  = (const float*)d_in[6];
    const float* ln1_g  = (const float*)d_in[7];
    const float* ln1_b  = (const float*)d_in[8];
    const float* ln2_g  = (const float*)d_in[9];
    const float* ln2_b  = (const float*)d_in[10];
    const float* cls_w  = (const float*)d_in[11];
    const float* cls_b  = (const float*)d_in[12];
    float* out = (float*)d_out;

    k_phaseB<<<128, 64>>>(x, proj_w, proj_b, rx, ry, ffn_w, ffn_b,
                          ln1_g, ln1_b, ln2_g, ln2_b, cls_b, out);
    k_final<<<dim3(16, 32), 256>>>(proj_w, proj_b, ln1_g, ln1_b, ln2_g, ln2_b,
                                   cls_w, out);
}